// round 13
// baseline (speedup 1.0000x reference)
#include <cuda_runtime.h>
#include <cuda_bf16.h>
#include <cstdint>
#include <math.h>

#define NB 16
#define NT 128
#define ND 384
#define NH 6
#define NDH 64
#define NM 2048                 // NB*NT

#define CH   786432             // NM*ND
#define WSZ  1572864            // NB*NH*NT*NT
#define WW   147456             // ND*ND
#define A3W  768                // [XRE|XIM] concat width
#define A3SZ 1572864            // 2048*768 = 2*CH

// ---------------- fp32 scratch layout ----------------
#define OFF_IH  0
#define OFF_QR  6144
#define OFF_QI  (OFF_QR + CH)
#define OFF_KR  (OFF_QI + CH)
#define OFF_KI  (OFF_KR + CH)
#define OFF_VR  (OFF_KI + CH)
#define OFF_VI  (OFF_VR + CH)
#define OFF_GRE (OFF_VI + CH)
#define OFF_GIM (OFF_GRE + CH)
#define TOTALF  (OFF_GIM + CH)

// ---------------- bf16 scratch layout ----------------
#define BF_RH   0
#define BF_RL   ((size_t)CH)
#define BF_IMH  ((size_t)2*CH)
#define BF_IML  ((size_t)3*CH)
#define BF_ARH  ((size_t)4*CH)
#define BF_ARL  ((size_t)5*CH)
#define BF_AIH  ((size_t)6*CH)
#define BF_AIL  ((size_t)7*CH)
#define BF_A3H  ((size_t)8*CH)               // 2048 x 768 hi
#define BF_A3L  (BF_A3H + (size_t)A3SZ)      // lo
#define BF_W    (BF_A3L + (size_t)A3SZ)      // 4 weights (Wq,Wk,Wv,Wo) x (hi WW, lo WW)
#define BF_CATR (BF_W + 8*(size_t)WW)        // [W1r|-W1i] 384x768 hi,lo
#define BF_CATI (BF_CATR + 4*(size_t)WW)     // [W1i| W1r] 384x768 hi,lo
#define BF_Q    (BF_CATI + 4*(size_t)WW)     // 4 arrays (QR,QI,KR,KI) x (hi CH, lo CH)
#define TOTB    (BF_Q + 8*(size_t)CH)

__device__ float g_scratch[TOTALF];
__device__ __align__(16) __nv_bfloat16 g_bf[TOTB];

// ======================= helpers =======================
__device__ __forceinline__ uint32_t smem_u32(const void* p) {
    uint32_t a;
    asm("{ .reg .u64 t; cvta.to.shared.u64 t, %1; cvt.u32.u64 %0, t; }" : "=r"(a) : "l"(p));
    return a;
}

__device__ __forceinline__ float blocksum128(float v, float* sbuf) {
    #pragma unroll
    for (int o = 16; o; o >>= 1) v += __shfl_xor_sync(0xffffffffu, v, o);
    if ((threadIdx.x & 31) == 0) sbuf[threadIdx.x >> 5] = v;
    __syncthreads();
    float r = sbuf[0] + sbuf[1] + sbuf[2] + sbuf[3];
    __syncthreads();
    return r;
}
__device__ __forceinline__ float gelu_exact(float x) {
    return 0.5f * x * (1.0f + erff(x * 0.7071067811865475f));
}
__device__ __forceinline__ void split_store(__nv_bfloat16* ph, __nv_bfloat16* pl, float v) {
    __nv_bfloat16 h = __float2bfloat16(v);
    *ph = h;
    *pl = __float2bfloat16(v - __bfloat162float(h));
}

#define LDSM4(r0, r1, r2, r3, a) \
    asm volatile("ldmatrix.sync.aligned.m8n8.x4.shared.b16 {%0,%1,%2,%3}, [%4];" \
                 : "=r"(r0), "=r"(r1), "=r"(r2), "=r"(r3) : "r"(a))

#define MMA16816(c, a, b) \
    asm volatile("mma.sync.aligned.m16n8k16.row.col.f32.bf16.bf16.f32 " \
                 "{%0,%1,%2,%3}, {%4,%5,%6,%7}, {%8,%9}, {%0,%1,%2,%3};" \
                 : "+f"((c)[0]), "+f"((c)[1]), "+f"((c)[2]), "+f"((c)[3]) \
                 : "r"((a)[0]), "r"((a)[1]), "r"((a)[2]), "r"((a)[3]), \
                   "r"((b)[0]), "r"((b)[1]))

#define CP_ASYNC16(dst, src) \
    asm volatile("cp.async.cg.shared.global [%0], [%1], 16;" :: "r"(dst), "l"(src))
#define CP_COMMIT() asm volatile("cp.async.commit_group;")
#define CP_WAIT1()  asm volatile("cp.async.wait_group 1;")
#define CP_WAIT0()  asm volatile("cp.async.wait_group 0;")

// ======================= mma.sync batched GEMM =======================
struct GemmOp {
    const __nv_bfloat16 *ah, *al, *bh, *bl;
    const float *bias, *bias2; float bscale, bscale2;
    float* out;                       // fp32 output (nullable)
    __nv_bfloat16 *outh, *outl;       // bf16 hi/lo output (nullable)
    int K, lda, ldo, gelu;
};
struct GemmBatch { GemmOp op[6]; };

// smem: 2 stages x 4 matrices x 128 rows x 40 bf16 (pad 32->40)
#define SMS 40
#define MAT_ELE (128 * SMS)           // 5120
#define STG_ELE (4 * MAT_ELE)         // 20480
#define MMA_SMEM (2 * STG_ELE * 2)    // 81920 B

__global__ void __launch_bounds__(256, 2) mma_gemm(GemmBatch batch) {
    extern __shared__ __nv_bfloat16 sm[];
    uint32_t smb = smem_u32(sm);
    const GemmOp op = batch.op[blockIdx.z];
    const int tid = threadIdx.x, lane = tid & 31, warp = tid >> 5;
    const int m0 = blockIdx.y * 128, n0 = blockIdx.x * 128;
    const int m0w = (warp & 1) * 64, n0w = (warp >> 1) * 32;
    const int Kd = op.K, lda = op.lda;
    const int nchunks = Kd >> 5;

    const int aBase = (m0w + (lane & 15)) * SMS + (lane >> 4) * 8;
    const int bBase = (n0w + ((lane >> 4) & 1) * 8 + (lane & 7)) * SMS + ((lane >> 3) & 1) * 8;

    float acc[4][4][4];
    #pragma unroll
    for (int i = 0; i < 4; i++)
        #pragma unroll
        for (int j = 0; j < 4; j++)
            #pragma unroll
            for (int q = 0; q < 4; q++) acc[i][j][q] = 0.f;

    auto load_stage = [&](int c, int s) {
        int kc = c * 32;
        #pragma unroll
        for (int mat = 0; mat < 4; mat++) {
            const __nv_bfloat16* src = (mat == 0) ? op.ah : (mat == 1) ? op.al
                                     : (mat == 2) ? op.bh : op.bl;
            int rb = (mat < 2) ? m0 : n0;
            int stride = (mat < 2) ? lda : Kd;
            #pragma unroll
            for (int i = 0; i < 2; i++) {
                int l = tid + 256 * i;          // 0..511
                int row = l >> 2, c8 = l & 3;
                const __nv_bfloat16* g = src + (size_t)(rb + row) * stride + kc + c8 * 8;
                uint32_t d = smb + (uint32_t)(s * STG_ELE + mat * MAT_ELE + row * SMS + c8 * 8) * 2;
                CP_ASYNC16(d, g);
            }
        }
        CP_COMMIT();
    };

    load_stage(0, 0);

    for (int c = 0; c < nchunks; c++) {
        if (c + 1 < nchunks) { load_stage(c + 1, (c + 1) & 1); CP_WAIT1(); }
        else                 { CP_WAIT0(); }
        __syncthreads();

        uint32_t stb = smb + (uint32_t)((c & 1) * STG_ELE) * 2;
        #pragma unroll
        for (int ks = 0; ks < 2; ks++) {
            uint32_t bhf[4][2], blf[4][2];
            #pragma unroll
            for (int pr = 0; pr < 2; pr++) {
                uint32_t addr = stb + (uint32_t)(2 * MAT_ELE + bBase + pr * 16 * SMS + ks * 16) * 2;
                uint32_t r0, r1, r2, r3;
                LDSM4(r0, r1, r2, r3, addr);
                bhf[2*pr][0] = r0; bhf[2*pr][1] = r1;
                bhf[2*pr+1][0] = r2; bhf[2*pr+1][1] = r3;
                LDSM4(r0, r1, r2, r3, addr + MAT_ELE * 2);
                blf[2*pr][0] = r0; blf[2*pr][1] = r1;
                blf[2*pr+1][0] = r2; blf[2*pr+1][1] = r3;
            }
            #pragma unroll
            for (int mf = 0; mf < 4; mf++) {
                uint32_t ah4[4], al4[4];
                uint32_t addr = stb + (uint32_t)(aBase + mf * 16 * SMS + ks * 16) * 2;
                LDSM4(ah4[0], ah4[1], ah4[2], ah4[3], addr);
                LDSM4(al4[0], al4[1], al4[2], al4[3], addr + MAT_ELE * 2);
                #pragma unroll
                for (int nf = 0; nf < 4; nf++) {
                    MMA16816(acc[mf][nf], ah4, bhf[nf]);
                    MMA16816(acc[mf][nf], ah4, blf[nf]);
                    MMA16816(acc[mf][nf], al4, bhf[nf]);
                }
            }
        }
        __syncthreads();
    }

    // ---- epilogue ----
    #pragma unroll
    for (int mf = 0; mf < 4; mf++) {
        #pragma unroll
        for (int nf = 0; nf < 4; nf++) {
            int r0 = m0 + m0w + mf * 16 + (lane >> 2);
            int col = n0 + n0w + nf * 8 + (lane & 3) * 2;
            float v0 = acc[mf][nf][0], v1 = acc[mf][nf][1];
            float v2 = acc[mf][nf][2], v3 = acc[mf][nf][3];
            if (op.bias) {
                float bb0 = op.bscale * op.bias[col], bb1 = op.bscale * op.bias[col + 1];
                v0 += bb0; v1 += bb1; v2 += bb0; v3 += bb1;
            }
            if (op.bias2) {
                float bb0 = op.bscale2 * op.bias2[col], bb1 = op.bscale2 * op.bias2[col + 1];
                v0 += bb0; v1 += bb1; v2 += bb0; v3 += bb1;
            }
            if (op.gelu) {
                v0 = gelu_exact(v0); v1 = gelu_exact(v1);
                v2 = gelu_exact(v2); v3 = gelu_exact(v3);
            }
            if (op.out) {
                *reinterpret_cast<float2*>(op.out + (size_t)r0 * op.ldo + col)       = make_float2(v0, v1);
                *reinterpret_cast<float2*>(op.out + (size_t)(r0 + 8) * op.ldo + col) = make_float2(v2, v3);
            }
            if (op.outh) {
                __nv_bfloat16 h0 = __float2bfloat16(v0), h1 = __float2bfloat16(v1);
                __nv_bfloat16 h2 = __float2bfloat16(v2), h3 = __float2bfloat16(v3);
                __nv_bfloat162 hp0; hp0.x = h0; hp0.y = h1;
                __nv_bfloat162 hp1; hp1.x = h2; hp1.y = h3;
                __nv_bfloat162 lp0; lp0.x = __float2bfloat16(v0 - __bfloat162float(h0));
                                    lp0.y = __float2bfloat16(v1 - __bfloat162float(h1));
                __nv_bfloat162 lp1; lp1.x = __float2bfloat16(v2 - __bfloat162float(h2));
                                    lp1.y = __float2bfloat16(v3 - __bfloat162float(h3));
                size_t i0 = (size_t)r0 * op.ldo + col, i1 = (size_t)(r0 + 8) * op.ldo + col;
                *reinterpret_cast<__nv_bfloat162*>(op.outh + i0) = hp0;
                *reinterpret_cast<__nv_bfloat162*>(op.outh + i1) = hp1;
                *reinterpret_cast<__nv_bfloat162*>(op.outl + i0) = lp0;
                *reinterpret_cast<__nv_bfloat162*>(op.outl + i1) = lp1;
            }
        }
    }
}

// ======================= fused prep kernel (+ih) =======================
__global__ void prep_all(const float* __restrict__ real, const float* __restrict__ imag,
                         const float* __restrict__ Wq, const float* __restrict__ Wk,
                         const float* __restrict__ Wv, const float* __restrict__ Wo,
                         const float* __restrict__ W1r, const float* __restrict__ W1i,
                         const float* __restrict__ iproj) {
    int bid = blockIdx.x, tid = threadIdx.x;
    if (bid < 6144) {
        int y = bid / 3072;
        int i = (bid - y * 3072) * 256 + tid;
        const float* s = y ? imag : real;
        size_t o = y ? BF_IMH : BF_RH;
        split_store(g_bf + o + i, g_bf + o + CH + i, s[i]);
    } else if (bid < 8448) {
        int t = bid - 6144;
        int y = t / 576;
        int i = (t - y * 576) * 256 + tid;
        const float* ws = (y == 0) ? Wq : (y == 1) ? Wk : (y == 2) ? Wv : Wo;
        size_t base = BF_W + (size_t)y * 2 * WW;
        split_store(g_bf + base + i, g_bf + base + WW + i, ws[i]);
    } else if (bid < 9600) {
        int i = (bid - 8448) * 256 + tid;      // < 2*WW
        int n = i / 768, k = i % 768;
        float vr = (k < 384) ? W1r[n*384 + k] : -W1i[n*384 + (k-384)];
        float vi = (k < 384) ? W1i[n*384 + k] :  W1r[n*384 + (k-384)];   // CATI = [W1i | W1r]
        split_store(g_bf + BF_CATR + i, g_bf + BF_CATR + 2*(size_t)WW + i, vr);
        split_store(g_bf + BF_CATI + i, g_bf + BF_CATI + 2*(size_t)WW + i, vi);
    } else {
        int b = bid - 9600;
        __shared__ float sred[8];
        __shared__ float sn3;
        if (tid == 0) {
            float a = iproj[b*128+0], c = iproj[b*128+1], d = iproj[b*128+2];
            sn3 = sqrtf(a*a + c*c + d*d);
        }
        __syncthreads();
        float w = (tid < 128) ? (iproj[b*128 + tid] / sn3) : 0.f;
        float p = w * w;
        #pragma unroll
        for (int o = 16; o; o >>= 1) p += __shfl_xor_sync(0xffffffffu, p, o);
        if ((tid & 31) == 0) sred[tid >> 5] = p;
        __syncthreads();
        float sum = 0.f;
        #pragma unroll
        for (int ww = 0; ww < 8; ww++) sum += sred[ww];
        float nf = sqrtf(3.0f * sum);
        if (tid < 128) {
            float val = w / nf;
            float* ih = g_scratch + OFF_IH + b*ND;
            ih[tid] = val; ih[tid+128] = val; ih[tid+256] = val;
        }
    }
}

// ======================= K3: deflation -> bf16 hi/lo =======================
__global__ void ortho_kernel() {
    __shared__ float sbuf[4];
    int y = blockIdx.y;                      // 0=QR 1=QI 2=KR 3=KI
    const float* arr = g_scratch + OFF_QR + (size_t)y * CH;
    __nv_bfloat16* oh = g_bf + BF_Q + (size_t)y * 2 * CH;
    __nv_bfloat16* ol = oh + CH;
    int row = blockIdx.x, t = threadIdx.x, b = row >> 7;
    const float* ih = g_scratch + OFF_IH + b*ND;
    float q0 = arr[row*ND + t], q1 = arr[row*ND + t + 128], q2 = arr[row*ND + t + 256];
    float i0 = ih[t], i1 = ih[t+128], i2 = ih[t+256];
    float dot = blocksum128(q0*i0 + q1*i1 + q2*i2, sbuf);
    split_store(oh + (size_t)row*ND + t,       ol + (size_t)row*ND + t,       q0 - dot*i0);
    split_store(oh + (size_t)row*ND + t + 128, ol + (size_t)row*ND + t + 128, q1 - dot*i1);
    split_store(oh + (size_t)row*ND + t + 256, ol + (size_t)row*ND + t + 256, q2 - dot*i2);
}

// ======================= K4: scores via mma.sync + softmax =======================
// Ss uses stride 132 (16B-aligned rows): 128*132*4 = 67584 B <= tile phase 73728 B
#define QH_T 0
#define QL_T 9216
#define KH_T 18432
#define KL_T 27648
#define SC2_SMEM 73728
#define SSTR 132

__global__ void __launch_bounds__(256, 2) scores_mma(float* __restrict__ wout) {
    extern __shared__ char smraw[];
    __nv_bfloat16* smb16 = reinterpret_cast<__nv_bfloat16*>(smraw);
    float* Ss = reinterpret_cast<float*>(smraw);
    uint32_t smb = smem_u32(smraw);
    int h = blockIdx.x, b = blockIdx.y, p = blockIdx.z, tid = threadIdx.x;
    int lane = tid & 31, warp = tid >> 5;

    const __nv_bfloat16* Qbase = g_bf + BF_Q + (size_t)(((p >> 1) & 1) * 2) * CH;
    const __nv_bfloat16* Kbase = g_bf + BF_Q + (size_t)((2 + (p & 1)) * 2) * CH;

    for (int l = tid; l < 4096; l += 256) {
        int mat = l >> 10, v = l & 1023;
        int row = v >> 3, col = (v & 7) * 8;
        const __nv_bfloat16* src = (mat == 0) ? Qbase : (mat == 1) ? Qbase + CH
                                  : (mat == 2) ? Kbase : Kbase + CH;
        uint4 val = *reinterpret_cast<const uint4*>(src + (size_t)(b*NT + row) * ND + h*NDH + col);
        *reinterpret_cast<uint4*>(smb16 + mat * 9216 + row * 72 + col) = val;
    }
    __syncthreads();

    const int mrow = (warp & 1) * 64, ncol = (warp >> 1) * 32;
    const int aBase = (mrow + (lane & 15)) * 72 + (lane >> 4) * 8;
    const int bBase = (ncol + ((lane >> 4) & 1) * 8 + (lane & 7)) * 72 + ((lane >> 3) & 1) * 8;

    float acc[4][4][4];
    #pragma unroll
    for (int i = 0; i < 4; i++)
        #pragma unroll
        for (int j = 0; j < 4; j++)
            #pragma unroll
            for (int q = 0; q < 4; q++) acc[i][j][q] = 0.f;

    #pragma unroll
    for (int ks = 0; ks < 4; ks++) {
        uint32_t bhf[4][2], blf[4][2];
        #pragma unroll
        for (int pr = 0; pr < 2; pr++) {
            uint32_t addr = smb + (uint32_t)(KH_T + bBase + pr * 16 * 72 + ks * 16) * 2;
            uint32_t r0, r1, r2, r3;
            LDSM4(r0, r1, r2, r3, addr);
            bhf[2*pr][0] = r0; bhf[2*pr][1] = r1;
            bhf[2*pr+1][0] = r2; bhf[2*pr+1][1] = r3;
            LDSM4(r0, r1, r2, r3, addr + (KL_T - KH_T) * 2);
            blf[2*pr][0] = r0; blf[2*pr][1] = r1;
            blf[2*pr+1][0] = r2; blf[2*pr+1][1] = r3;
        }
        #pragma unroll
        for (int mf = 0; mf < 4; mf++) {
            uint32_t ah4[4], al4[4];
            uint32_t addr = smb + (uint32_t)(QH_T + aBase + mf * 16 * 72 + ks * 16) * 2;
            LDSM4(ah4[0], ah4[1], ah4[2], ah4[3], addr);
            LDSM4(al4[0], al4[1], al4[2], al4[3], addr + (QL_T - QH_T) * 2);
            #pragma unroll
            for (int nf = 0; nf < 4; nf++) {
                MMA16816(acc[mf][nf], ah4, bhf[nf]);
                MMA16816(acc[mf][nf], ah4, blf[nf]);
                MMA16816(acc[mf][nf], al4, bhf[nf]);
            }
        }
    }
    __syncthreads();

    #pragma unroll
    for (int mf = 0; mf < 4; mf++) {
        #pragma unroll
        for (int nf = 0; nf < 4; nf++) {
            int r = mrow + mf * 16 + (lane >> 2);
            int cc = ncol + nf * 8 + (lane & 3) * 2;
            Ss[r * SSTR + cc]           = acc[mf][nf][0] * 0.125f;
            Ss[r * SSTR + cc + 1]       = acc[mf][nf][1] * 0.125f;
            Ss[(r + 8) * SSTR + cc]     = acc[mf][nf][2] * 0.125f;
            Ss[(r + 8) * SSTR + cc + 1] = acc[mf][nf][3] * 0.125f;
        }
    }
    __syncthreads();

    const int s1t[4] = {0, 2, 3, 6};
    const int s2t[4] = {1, 4, 5, 7};
    for (int r = warp; r < 128; r += 8) {
        float4 vv = *reinterpret_cast<const float4*>(&Ss[r * SSTR + lane * 4]);
        float mx = fmaxf(fmaxf(vv.x, vv.y), fmaxf(vv.z, vv.w));
        #pragma unroll
        for (int o = 16; o; o >>= 1) mx = fmaxf(mx, __shfl_xor_sync(0xffffffffu, mx, o));
        float e0 = __expf(vv.x - mx), e1 = __expf(vv.y - mx);
        float e2 = __expf(vv.z - mx), e3 = __expf(vv.w - mx);
        float s = e0 + e1 + e2 + e3;
        #pragma unroll
        for (int o = 16; o; o >>= 1) s += __shfl_xor_sync(0xffffffffu, s, o);
        float inv = 1.0f / s;
        float4 wv = make_float4(e0 * inv, e1 * inv, e2 * inv, e3 * inv);
        size_t idx = (((size_t)b*NH + h)*NT + r)*NT + lane * 4;
        *reinterpret_cast<float4*>(wout + (size_t)s1t[p]*WSZ + idx) = wv;
        *reinterpret_cast<float4*>(wout + (size_t)s2t[p]*WSZ + idx) = wv;
    }
}

// ======================= K5: attention x V (16 q per block, float4 w) =======================
#define AV_SMEM ((8192*2 + 2048*2) * 4)

__global__ void __launch_bounds__(256, 2) av_kernel(const float* __restrict__ wout) {
    extern __shared__ float smf[];
    float* Vsr = smf;
    float* Vsi = smf + 8192;
    float* sWA = smf + 16384;
    float* sWB = smf + 18432;
    int qt = blockIdx.x, h = blockIdx.y, b = blockIdx.z, tid = threadIdx.x;

    const float* Vr = g_scratch + OFF_VR;
    const float* Vi = g_scratch + OFF_VI;
    for (int l = tid; l < 8192; l += 256) {
        int k = l >> 6, d = l & 63;
        int gi = (b*NT + k)*ND + h*NDH + d;
        Vsr[l] = Vr[gi]; Vsi[l] = Vi[gi];
    }
    for (int l = tid; l < 2048; l += 256) {
        int ql = l >> 7, kk = l & 127;
        int q = qt*16 + ql;
        size_t idx = (((size_t)b*NH + h)*NT + q)*NT + kk;
        sWA[l] = wout[idx] - wout[6*(size_t)WSZ + idx];
        sWB[l] = wout[2*(size_t)WSZ + idx] + wout[3*(size_t)WSZ + idx];
    }
    __syncthreads();

    int d = tid & 63, qi = tid >> 6;
    float ar[4] = {0,0,0,0}, ai[4] = {0,0,0,0};
    for (int kk = 0; kk < 128; kk += 4) {
        float wa4[4][4], wb4[4][4];
        #pragma unroll
        for (int j = 0; j < 4; j++) {
            float4 ta = *reinterpret_cast<const float4*>(&sWA[(qi*4 + j)*128 + kk]);
            float4 tb = *reinterpret_cast<const float4*>(&sWB[(qi*4 + j)*128 + kk]);
            wa4[j][0] = ta.x; wa4[j][1] = ta.y; wa4[j][2] = ta.z; wa4[j][3] = ta.w;
            wb4[j][0] = tb.x; wb4[j][1] = tb.y; wb4[j][2] = tb.z; wb4[j][3] = tb.w;
        }
        #pragma unroll
        for (int u = 0; u < 4; u++) {
            float vr = Vsr[(kk+u)*64 + d], vi = Vsi[(kk+u)*64 + d];
            #pragma unroll
            for (int j = 0; j < 4; j++) {
                ar[j] += wa4[j][u]*vr - wb4[j][u]*vi;
                ai[j] += wb4[j][u]*vr + wa4[j][u]*vi;
            }
        }
    }
    #pragma unroll
    for (int j = 0; j < 4; j++) {
        int q = qt*16 + qi*4 + j;
        size_t go = (size_t)(b*NT + q)*ND + h*NDH + d;
        split_store(g_bf + BF_ARH + go, g_bf + BF_ARL + go, ar[j]);
        split_store(g_bf + BF_AIH + go, g_bf + BF_AIL + go, ai[j]);
    }
}

// ======================= K9: final scalars + layernorm =======================
__global__ void final_kernel(const float* __restrict__ real, const float* __restrict__ imag,
                             const float* __restrict__ W2r, const float* __restrict__ b2r,
                             const float* __restrict__ W2i, const float* __restrict__ b2i,
                             const float* __restrict__ g1,  const float* __restrict__ be1,
                             float* __restrict__ out) {
    int row = blockIdx.x, t = threadIdx.x;
    __shared__ float sbuf[4];
    const float* gre = g_scratch + OFF_GRE + (size_t)row*ND;
    const float* gim = g_scratch + OFF_GIM + (size_t)row*ND;
    const float* re  = real + (size_t)row*ND;
    const float* im  = imag + (size_t)row*ND;

    float grev[3], gimv[3], rev[3], imv[3], w2rv[3], w2iv[3];
    #pragma unroll
    for (int j = 0; j < 3; j++) {
        int d = t + 128*j;
        grev[j] = gre[d]; gimv[j] = gim[d];
        rev[j]  = re[d];  imv[j]  = im[d];
        w2rv[j] = W2r[d]; w2iv[j] = W2i[d];
    }
    float p0=0,p1=0,p2=0,p3=0,p4=0,p5=0;
    #pragma unroll
    for (int j = 0; j < 3; j++) {
        p0 += grev[j]*w2rv[j];
        p1 += gimv[j]*w2iv[j];
        p2 += gimv[j]*w2rv[j];
        p3 += grev[j]*w2iv[j];
        p4 += rev[j]*rev[j] + imv[j]*imv[j];
        p5 -= (rev[j] + imv[j]) * imv[j];
    }
    float d0 = blocksum128(p0, sbuf);
    float d1 = blocksum128(p1, sbuf);
    float d2 = blocksum128(p2, sbuf);
    float d3 = blocksum128(p3, sbuf);
    float d4 = blocksum128(p4, sbuf);   // F_re
    float d5 = blocksum128(p5, sbuf);   // F_im

    float sre  = d0 + b2r[0] - (d1 + b2i[0]);
    float sim  = d2 + b2r[0] + (d3 + b2i[0]);
    float s2   = sre*sre + sim*sim;
    float simn = -(s2*sim) - sim*sim;
    float denom = d4*d4 + d5*d5;
    float Wc = (s2*d4 + simn*d5) / denom;

    float xr[3], xi[3];
    #pragma unroll
    for (int j = 0; j < 3; j++) {
        xr[j] = Wc * (rev[j] - imv[j]);
        xi[j] = 2.0f * Wc * imv[j];
    }
    float mr = blocksum128(xr[0]+xr[1]+xr[2], sbuf) * (1.0f/ND);
    float vrp = 0.f;
    #pragma unroll
    for (int j = 0; j < 3; j++) { float dd = xr[j]-mr; vrp += dd*dd; }
    float vr = blocksum128(vrp, sbuf) * (1.0f/ND);
    float rsr = rsqrtf(vr + 1e-5f);
    float mi = blocksum128(xi[0]+xi[1]+xi[2], sbuf) * (1.0f/ND);
    float vip = 0.f;
    #pragma unroll
    for (int j = 0; j < 3; j++) { float dd = xi[j]-mi; vip += dd*dd; }
    float vi = blocksum128(vip, sbuf) * (1.0f/ND);
    float rsi = rsqrtf(vi + 1e-5f);

    #pragma unroll
    for (int j = 0; j < 3; j++) {
        int d = t + 128*j;
        out[(size_t)row*ND + d]      = (xr[j]-mr)*rsr*g1[d] + be1[d];
        out[CH + (size_t)row*ND + d] = (xi[j]-mi)*rsi*g1[d] + be1[d];
    }
}

// ======================= host launcher =======================
extern "C" void kernel_launch(void* const* d_in, const int* in_sizes, int n_in,
                              void* d_out, int out_size) {
    const float* real  = (const float*)d_in[0];
    const float* imag  = (const float*)d_in[1];
    const float* iproj = (const float*)d_in[2];
    const float* Wq = (const float*)d_in[3];  const float* bq = (const float*)d_in[4];
    const float* Wk = (const float*)d_in[5];  const float* bk = (const float*)d_in[6];
    const float* Wv = (const float*)d_in[7];  const float* bv = (const float*)d_in[8];
    const float* Wo = (const float*)d_in[9];  const float* bo = (const float*)d_in[10];
    const float* W1r = (const float*)d_in[11]; const float* b1r = (const float*)d_in[12];
    const float* W1i = (const float*)d_in[13]; const float* b1i = (const float*)d_in[14];
    const float* W2r = (const float*)d_in[15]; const float* b2r = (const float*)d_in[16];
    const float* W2i = (const float*)d_in[17]; const float* b2i = (const float*)d_in[18];
    const float* g1  = (const float*)d_in[19]; const float* be1 = (const float*)d_in[20];
    float* out = (float*)d_out;

    float* S = nullptr;
    __nv_bfloat16* Bp = nullptr;
    cudaGetSymbolAddress((void**)&S, g_scratch);
    cudaGetSymbolAddress((void**)&Bp, g_bf);

    cudaFuncSetAttribute(scores_mma, cudaFuncAttributeMaxDynamicSharedMemorySize, SC2_SMEM);
    cudaFuncSetAttribute(av_kernel,  cudaFuncAttributeMaxDynamicSharedMemorySize, AV_SMEM);
    cudaFuncSetAttribute(mma_gemm,   cudaFuncAttributeMaxDynamicSharedMemorySize, MMA_SMEM);

    __nv_bfloat16* WH[4]; __nv_bfloat16* WL[4];
    for (int y = 0; y < 4; y++) {
        WH[y] = Bp + BF_W + (size_t)y * 2 * WW;
        WL[y] = WH[y] + WW;
    }
    __nv_bfloat16* CRH = Bp + BF_CATR;            __nv_bfloat16* CRL = CRH + 2*(size_t)WW;
    __nv_bfloat16* CIH = Bp + BF_CATI;            __nv_bfloat16* CIL = CIH + 2*(size_t)WW;

    // 1) fused prep (acts, weights, W1 concats, ih)
    prep_all<<<9616, 256>>>(real, imag, Wq, Wk, Wv, Wo, W1r, W1i, iproj);

    // 2) stage-1: six projection GEMMs (fp32 outputs)
    GemmBatch s1;
    const __nv_bfloat16* AH2[2] = { Bp + BF_RH, Bp + BF_IMH };
    const __nv_bfloat16* AL2[2] = { Bp + BF_RL, Bp + BF_IML };
    const float* biases[3] = { bq, bk, bv };
    size_t outs[6] = { OFF_QR, OFF_QI, OFF_KR, OFF_KI, OFF_VR, OFF_VI };
    for (int o = 0; o < 6; o++) {
        int w = o >> 1, a = o & 1;
        s1.op[o] = { AH2[a], AL2[a], WH[w], WL[w], biases[w], nullptr, 1.0f, 0.f,
                     S + outs[o], nullptr, nullptr, ND, ND, ND, 0 };
    }
    mma_gemm<<<dim3(3, 16, 6), 256, MMA_SMEM>>>(s1);

    // 3) deflate Q/K -> bf16 hi/lo
    ortho_kernel<<<dim3(NM, 4), 128>>>();

    // 4) scores via mma + softmax -> all 8 weight output sections
    scores_mma<<<dim3(NH, NB, 4), 256, SC2_SMEM>>>(out + 2*(size_t)CH);

    // 5) attention x V -> bf16 hi/lo
    av_kernel<<<dim3(NT/16, NH, NB), 256, AV_SMEM>>>(out + 2*(size_t)CH);

    // 6) stage-2: Wo GEMMs -> A3 [XRE | XIM] (2048 x 768, no dup)
    GemmBatch s2;
    s2.op[0] = { Bp + BF_ARH, Bp + BF_ARL, WH[3], WL[3], bo, nullptr, -2.0f, 0.f,
                 nullptr, Bp + BF_A3H, Bp + BF_A3L, ND, ND, A3W, 0 };
    s2.op[1] = { Bp + BF_AIH, Bp + BF_AIL, WH[3], WL[3], bo, nullptr,  2.0f, 0.f,
                 nullptr, Bp + BF_A3H + 384, Bp + BF_A3L + 384, ND, ND, A3W, 0 };
    mma_gemm<<<dim3(3, 16, 2), 256, MMA_SMEM>>>(s2);

    // 7) stage-3: fused W1 complex layer (K=768, both ops read same A3) + bias + GELU
    GemmBatch s3;
    s3.op[0] = { Bp + BF_A3H, Bp + BF_A3L, CRH, CRL, b1r, b1i, 1.0f, -1.0f,
                 S + OFF_GRE, nullptr, nullptr, A3W, A3W, ND, 1 };
    s3.op[1] = { Bp + BF_A3H, Bp + BF_A3L, CIH, CIL, b1r, b1i, 1.0f,  1.0f,
                 S + OFF_GIM, nullptr, nullptr, A3W, A3W, ND, 1 };
    mma_gemm<<<dim3(3, 16, 2), 256, MMA_SMEM>>>(s3);

    // 8) final scalars + layernorm
    final_kernel<<<NM, 128>>>(real, imag, W2r, b2r, W2i, b2i, g1, be1, out);
}

// round 14
// speedup vs baseline: 1.0783x; 1.0783x over previous
#include <cuda_runtime.h>
#include <cuda_bf16.h>
#include <cstdint>
#include <math.h>

#define NB 16
#define NT 128
#define ND 384
#define NH 6
#define NDH 64
#define NM 2048                 // NB*NT

#define CH   786432             // NM*ND
#define WSZ  1572864            // NB*NH*NT*NT
#define WW   147456             // ND*ND
#define A3W  768                // [XRE|XIM] concat width
#define A3SZ 1572864            // 2048*768 = 2*CH

// ---------------- fp32 scratch layout ----------------
#define OFF_IH  0
#define OFF_QR  6144
#define OFF_QI  (OFF_QR + CH)
#define OFF_KR  (OFF_QI + CH)
#define OFF_KI  (OFF_KR + CH)
#define OFF_VR  (OFF_KI + CH)
#define OFF_VI  (OFF_VR + CH)
#define OFF_GRE (OFF_VI + CH)
#define OFF_GIM (OFF_GRE + CH)
#define TOTALF  (OFF_GIM + CH)

// ---------------- bf16 scratch layout ----------------
#define BF_RH   0
#define BF_RL   ((size_t)CH)
#define BF_IMH  ((size_t)2*CH)
#define BF_IML  ((size_t)3*CH)
#define BF_ARH  ((size_t)4*CH)
#define BF_ARL  ((size_t)5*CH)
#define BF_AIH  ((size_t)6*CH)
#define BF_AIL  ((size_t)7*CH)
#define BF_A3H  ((size_t)8*CH)               // 2048 x 768 hi
#define BF_A3L  (BF_A3H + (size_t)A3SZ)      // lo
#define BF_W    (BF_A3L + (size_t)A3SZ)      // 4 weights (Wq,Wk,Wv,Wo) x (hi WW, lo WW)
#define BF_CATR (BF_W + 8*(size_t)WW)        // [W1r|-W1i] 384x768 hi,lo
#define BF_CATI (BF_CATR + 4*(size_t)WW)     // [W1i| W1r] 384x768 hi,lo
#define BF_Q    (BF_CATI + 4*(size_t)WW)     // 4 arrays (QR,QI,KR,KI) x (hi CH, lo CH)
#define TOTB    (BF_Q + 8*(size_t)CH)

__device__ float g_scratch[TOTALF];
__device__ __align__(16) __nv_bfloat16 g_bf[TOTB];

// ======================= helpers =======================
__device__ __forceinline__ uint32_t smem_u32(const void* p) {
    uint32_t a;
    asm("{ .reg .u64 t; cvta.to.shared.u64 t, %1; cvt.u32.u64 %0, t; }" : "=r"(a) : "l"(p));
    return a;
}

__device__ __forceinline__ float blocksum128(float v, float* sbuf) {
    #pragma unroll
    for (int o = 16; o; o >>= 1) v += __shfl_xor_sync(0xffffffffu, v, o);
    if ((threadIdx.x & 31) == 0) sbuf[threadIdx.x >> 5] = v;
    __syncthreads();
    float r = sbuf[0] + sbuf[1] + sbuf[2] + sbuf[3];
    __syncthreads();
    return r;
}
__device__ __forceinline__ float gelu_exact(float x) {
    return 0.5f * x * (1.0f + erff(x * 0.7071067811865475f));
}
__device__ __forceinline__ void split_store(__nv_bfloat16* ph, __nv_bfloat16* pl, float v) {
    __nv_bfloat16 h = __float2bfloat16(v);
    *ph = h;
    *pl = __float2bfloat16(v - __bfloat162float(h));
}

#define LDSM4(r0, r1, r2, r3, a) \
    asm volatile("ldmatrix.sync.aligned.m8n8.x4.shared.b16 {%0,%1,%2,%3}, [%4];" \
                 : "=r"(r0), "=r"(r1), "=r"(r2), "=r"(r3) : "r"(a))

#define MMA16816(c, a, b) \
    asm volatile("mma.sync.aligned.m16n8k16.row.col.f32.bf16.bf16.f32 " \
                 "{%0,%1,%2,%3}, {%4,%5,%6,%7}, {%8,%9}, {%0,%1,%2,%3};" \
                 : "+f"((c)[0]), "+f"((c)[1]), "+f"((c)[2]), "+f"((c)[3]) \
                 : "r"((a)[0]), "r"((a)[1]), "r"((a)[2]), "r"((a)[3]), \
                   "r"((b)[0]), "r"((b)[1]))

#define CP_ASYNC16(dst, src) \
    asm volatile("cp.async.cg.shared.global [%0], [%1], 16;" :: "r"(dst), "l"(src))
#define CP_COMMIT() asm volatile("cp.async.commit_group;")
#define CP_WAIT1()  asm volatile("cp.async.wait_group 1;")
#define CP_WAIT0()  asm volatile("cp.async.wait_group 0;")

// ======================= mma.sync batched GEMM =======================
struct GemmOp {
    const __nv_bfloat16 *ah, *al, *bh, *bl;
    const float *bias, *bias2; float bscale, bscale2;
    float* out;                       // fp32 output (nullable)
    __nv_bfloat16 *outh, *outl;       // bf16 hi/lo output (nullable)
    int K, lda, ldo, gelu;
};
struct GemmBatch { GemmOp op[6]; };

// smem: 2 stages x 4 matrices x 128 rows x 40 bf16 (pad 32->40)
#define SMS 40
#define MAT_ELE (128 * SMS)           // 5120
#define STG_ELE (4 * MAT_ELE)         // 20480
#define MMA_SMEM (2 * STG_ELE * 2)    // 81920 B

__global__ void __launch_bounds__(256, 2) mma_gemm(GemmBatch batch) {
    extern __shared__ __nv_bfloat16 sm[];
    uint32_t smb = smem_u32(sm);
    const GemmOp op = batch.op[blockIdx.z];
    const int tid = threadIdx.x, lane = tid & 31, warp = tid >> 5;
    const int m0 = blockIdx.y * 128, n0 = blockIdx.x * 128;
    const int m0w = (warp & 1) * 64, n0w = (warp >> 1) * 32;
    const int Kd = op.K, lda = op.lda;
    const int nchunks = Kd >> 5;

    const int aBase = (m0w + (lane & 15)) * SMS + (lane >> 4) * 8;
    const int bBase = (n0w + ((lane >> 4) & 1) * 8 + (lane & 7)) * SMS + ((lane >> 3) & 1) * 8;

    float acc[4][4][4];
    #pragma unroll
    for (int i = 0; i < 4; i++)
        #pragma unroll
        for (int j = 0; j < 4; j++)
            #pragma unroll
            for (int q = 0; q < 4; q++) acc[i][j][q] = 0.f;

    auto load_stage = [&](int c, int s) {
        int kc = c * 32;
        #pragma unroll
        for (int mat = 0; mat < 4; mat++) {
            const __nv_bfloat16* src = (mat == 0) ? op.ah : (mat == 1) ? op.al
                                     : (mat == 2) ? op.bh : op.bl;
            int rb = (mat < 2) ? m0 : n0;
            int stride = (mat < 2) ? lda : Kd;
            #pragma unroll
            for (int i = 0; i < 2; i++) {
                int l = tid + 256 * i;          // 0..511
                int row = l >> 2, c8 = l & 3;
                const __nv_bfloat16* g = src + (size_t)(rb + row) * stride + kc + c8 * 8;
                uint32_t d = smb + (uint32_t)(s * STG_ELE + mat * MAT_ELE + row * SMS + c8 * 8) * 2;
                CP_ASYNC16(d, g);
            }
        }
        CP_COMMIT();
    };

    load_stage(0, 0);

    for (int c = 0; c < nchunks; c++) {
        if (c + 1 < nchunks) { load_stage(c + 1, (c + 1) & 1); CP_WAIT1(); }
        else                 { CP_WAIT0(); }
        __syncthreads();

        uint32_t stb = smb + (uint32_t)((c & 1) * STG_ELE) * 2;
        #pragma unroll
        for (int ks = 0; ks < 2; ks++) {
            uint32_t bhf[4][2], blf[4][2];
            #pragma unroll
            for (int pr = 0; pr < 2; pr++) {
                uint32_t addr = stb + (uint32_t)(2 * MAT_ELE + bBase + pr * 16 * SMS + ks * 16) * 2;
                uint32_t r0, r1, r2, r3;
                LDSM4(r0, r1, r2, r3, addr);
                bhf[2*pr][0] = r0; bhf[2*pr][1] = r1;
                bhf[2*pr+1][0] = r2; bhf[2*pr+1][1] = r3;
                LDSM4(r0, r1, r2, r3, addr + MAT_ELE * 2);
                blf[2*pr][0] = r0; blf[2*pr][1] = r1;
                blf[2*pr+1][0] = r2; blf[2*pr+1][1] = r3;
            }
            #pragma unroll
            for (int mf = 0; mf < 4; mf++) {
                uint32_t ah4[4], al4[4];
                uint32_t addr = stb + (uint32_t)(aBase + mf * 16 * SMS + ks * 16) * 2;
                LDSM4(ah4[0], ah4[1], ah4[2], ah4[3], addr);
                LDSM4(al4[0], al4[1], al4[2], al4[3], addr + MAT_ELE * 2);
                #pragma unroll
                for (int nf = 0; nf < 4; nf++) {
                    MMA16816(acc[mf][nf], ah4, bhf[nf]);
                    MMA16816(acc[mf][nf], ah4, blf[nf]);
                    MMA16816(acc[mf][nf], al4, bhf[nf]);
                }
            }
        }
        __syncthreads();
    }

    // ---- epilogue ----
    #pragma unroll
    for (int mf = 0; mf < 4; mf++) {
        #pragma unroll
        for (int nf = 0; nf < 4; nf++) {
            int r0 = m0 + m0w + mf * 16 + (lane >> 2);
            int col = n0 + n0w + nf * 8 + (lane & 3) * 2;
            float v0 = acc[mf][nf][0], v1 = acc[mf][nf][1];
            float v2 = acc[mf][nf][2], v3 = acc[mf][nf][3];
            if (op.bias) {
                float bb0 = op.bscale * op.bias[col], bb1 = op.bscale * op.bias[col + 1];
                v0 += bb0; v1 += bb1; v2 += bb0; v3 += bb1;
            }
            if (op.bias2) {
                float bb0 = op.bscale2 * op.bias2[col], bb1 = op.bscale2 * op.bias2[col + 1];
                v0 += bb0; v1 += bb1; v2 += bb0; v3 += bb1;
            }
            if (op.gelu) {
                v0 = gelu_exact(v0); v1 = gelu_exact(v1);
                v2 = gelu_exact(v2); v3 = gelu_exact(v3);
            }
            if (op.out) {
                *reinterpret_cast<float2*>(op.out + (size_t)r0 * op.ldo + col)       = make_float2(v0, v1);
                *reinterpret_cast<float2*>(op.out + (size_t)(r0 + 8) * op.ldo + col) = make_float2(v2, v3);
            }
            if (op.outh) {
                __nv_bfloat16 h0 = __float2bfloat16(v0), h1 = __float2bfloat16(v1);
                __nv_bfloat16 h2 = __float2bfloat16(v2), h3 = __float2bfloat16(v3);
                __nv_bfloat162 hp0; hp0.x = h0; hp0.y = h1;
                __nv_bfloat162 hp1; hp1.x = h2; hp1.y = h3;
                __nv_bfloat162 lp0; lp0.x = __float2bfloat16(v0 - __bfloat162float(h0));
                                    lp0.y = __float2bfloat16(v1 - __bfloat162float(h1));
                __nv_bfloat162 lp1; lp1.x = __float2bfloat16(v2 - __bfloat162float(h2));
                                    lp1.y = __float2bfloat16(v3 - __bfloat162float(h3));
                size_t i0 = (size_t)r0 * op.ldo + col, i1 = (size_t)(r0 + 8) * op.ldo + col;
                *reinterpret_cast<__nv_bfloat162*>(op.outh + i0) = hp0;
                *reinterpret_cast<__nv_bfloat162*>(op.outh + i1) = hp1;
                *reinterpret_cast<__nv_bfloat162*>(op.outl + i0) = lp0;
                *reinterpret_cast<__nv_bfloat162*>(op.outl + i1) = lp1;
            }
        }
    }
}

// ======================= fused prep kernel (+ih) =======================
__global__ void prep_all(const float* __restrict__ real, const float* __restrict__ imag,
                         const float* __restrict__ Wq, const float* __restrict__ Wk,
                         const float* __restrict__ Wv, const float* __restrict__ Wo,
                         const float* __restrict__ W1r, const float* __restrict__ W1i,
                         const float* __restrict__ iproj) {
    int bid = blockIdx.x, tid = threadIdx.x;
    if (bid < 6144) {
        int y = bid / 3072;
        int i = (bid - y * 3072) * 256 + tid;
        const float* s = y ? imag : real;
        size_t o = y ? BF_IMH : BF_RH;
        split_store(g_bf + o + i, g_bf + o + CH + i, s[i]);
    } else if (bid < 8448) {
        int t = bid - 6144;
        int y = t / 576;
        int i = (t - y * 576) * 256 + tid;
        const float* ws = (y == 0) ? Wq : (y == 1) ? Wk : (y == 2) ? Wv : Wo;
        size_t base = BF_W + (size_t)y * 2 * WW;
        split_store(g_bf + base + i, g_bf + base + WW + i, ws[i]);
    } else if (bid < 9600) {
        int i = (bid - 8448) * 256 + tid;      // < 2*WW
        int n = i / 768, k = i % 768;
        float vr = (k < 384) ? W1r[n*384 + k] : -W1i[n*384 + (k-384)];
        float vi = (k < 384) ? W1i[n*384 + k] :  W1r[n*384 + (k-384)];   // CATI = [W1i | W1r]
        split_store(g_bf + BF_CATR + i, g_bf + BF_CATR + 2*(size_t)WW + i, vr);
        split_store(g_bf + BF_CATI + i, g_bf + BF_CATI + 2*(size_t)WW + i, vi);
    } else {
        int b = bid - 9600;
        __shared__ float sred[8];
        __shared__ float sn3;
        if (tid == 0) {
            float a = iproj[b*128+0], c = iproj[b*128+1], d = iproj[b*128+2];
            sn3 = sqrtf(a*a + c*c + d*d);
        }
        __syncthreads();
        float w = (tid < 128) ? (iproj[b*128 + tid] / sn3) : 0.f;
        float p = w * w;
        #pragma unroll
        for (int o = 16; o; o >>= 1) p += __shfl_xor_sync(0xffffffffu, p, o);
        if ((tid & 31) == 0) sred[tid >> 5] = p;
        __syncthreads();
        float sum = 0.f;
        #pragma unroll
        for (int ww = 0; ww < 8; ww++) sum += sred[ww];
        float nf = sqrtf(3.0f * sum);
        if (tid < 128) {
            float val = w / nf;
            float* ih = g_scratch + OFF_IH + b*ND;
            ih[tid] = val; ih[tid+128] = val; ih[tid+256] = val;
        }
    }
}

// ======================= K3: deflation -> bf16 hi/lo =======================
__global__ void ortho_kernel() {
    __shared__ float sbuf[4];
    int y = blockIdx.y;                      // 0=QR 1=QI 2=KR 3=KI
    const float* arr = g_scratch + OFF_QR + (size_t)y * CH;
    __nv_bfloat16* oh = g_bf + BF_Q + (size_t)y * 2 * CH;
    __nv_bfloat16* ol = oh + CH;
    int row = blockIdx.x, t = threadIdx.x, b = row >> 7;
    const float* ih = g_scratch + OFF_IH + b*ND;
    float q0 = arr[row*ND + t], q1 = arr[row*ND + t + 128], q2 = arr[row*ND + t + 256];
    float i0 = ih[t], i1 = ih[t+128], i2 = ih[t+256];
    float dot = blocksum128(q0*i0 + q1*i1 + q2*i2, sbuf);
    split_store(oh + (size_t)row*ND + t,       ol + (size_t)row*ND + t,       q0 - dot*i0);
    split_store(oh + (size_t)row*ND + t + 128, ol + (size_t)row*ND + t + 128, q1 - dot*i1);
    split_store(oh + (size_t)row*ND + t + 256, ol + (size_t)row*ND + t + 256, q2 - dot*i2);
}

// ======================= K4: scores via mma.sync, register softmax =======================
// smem: tiles 73728 B (QH/QL/KH/KL each 128x72 bf16) + pm 2048 B + ps 2048 B
#define QH_T 0
#define QL_T 9216
#define KH_T 18432
#define KL_T 27648
#define SC2_SMEM (73728 + 4096)

__global__ void __launch_bounds__(256, 2) scores_mma(float* __restrict__ wout) {
    extern __shared__ char smraw[];
    __nv_bfloat16* smb16 = reinterpret_cast<__nv_bfloat16*>(smraw);
    float* pm = reinterpret_cast<float*>(smraw + 73728);       // [128][4]
    float* ps = pm + 512;                                      // [128][4]
    uint32_t smb = smem_u32(smraw);
    int h = blockIdx.x, b = blockIdx.y, p = blockIdx.z, tid = threadIdx.x;
    int lane = tid & 31, warp = tid >> 5;

    const __nv_bfloat16* Qbase = g_bf + BF_Q + (size_t)(((p >> 1) & 1) * 2) * CH;
    const __nv_bfloat16* Kbase = g_bf + BF_Q + (size_t)((2 + (p & 1)) * 2) * CH;

    // cp.async tile load: 4096 x 16B chunks
    #pragma unroll
    for (int i = 0; i < 16; i++) {
        int l = tid + 256 * i;
        int mat = l >> 10, v = l & 1023;
        int row = v >> 3, col = (v & 7) * 8;
        const __nv_bfloat16* src = (mat == 0) ? Qbase : (mat == 1) ? Qbase + CH
                                  : (mat == 2) ? Kbase : Kbase + CH;
        const __nv_bfloat16* g = src + (size_t)(b*NT + row) * ND + h*NDH + col;
        uint32_t d = smb + (uint32_t)(mat * 9216 + row * 72 + col) * 2;
        CP_ASYNC16(d, g);
    }
    CP_COMMIT();
    CP_WAIT0();
    __syncthreads();

    const int mrow = (warp & 1) * 64, ncol = (warp >> 1) * 32;
    const int cg = warp >> 1;                 // column group 0..3
    const int aBase = (mrow + (lane & 15)) * 72 + (lane >> 4) * 8;
    const int bBase = (ncol + ((lane >> 4) & 1) * 8 + (lane & 7)) * 72 + ((lane >> 3) & 1) * 8;

    float acc[4][4][4];
    #pragma unroll
    for (int i = 0; i < 4; i++)
        #pragma unroll
        for (int j = 0; j < 4; j++)
            #pragma unroll
            for (int q = 0; q < 4; q++) acc[i][j][q] = 0.f;

    #pragma unroll
    for (int ks = 0; ks < 4; ks++) {
        uint32_t bhf[4][2], blf[4][2];
        #pragma unroll
        for (int pr = 0; pr < 2; pr++) {
            uint32_t addr = smb + (uint32_t)(KH_T + bBase + pr * 16 * 72 + ks * 16) * 2;
            uint32_t r0, r1, r2, r3;
            LDSM4(r0, r1, r2, r3, addr);
            bhf[2*pr][0] = r0; bhf[2*pr][1] = r1;
            bhf[2*pr+1][0] = r2; bhf[2*pr+1][1] = r3;
            LDSM4(r0, r1, r2, r3, addr + (KL_T - KH_T) * 2);
            blf[2*pr][0] = r0; blf[2*pr][1] = r1;
            blf[2*pr+1][0] = r2; blf[2*pr+1][1] = r3;
        }
        #pragma unroll
        for (int mf = 0; mf < 4; mf++) {
            uint32_t ah4[4], al4[4];
            uint32_t addr = smb + (uint32_t)(QH_T + aBase + mf * 16 * 72 + ks * 16) * 2;
            LDSM4(ah4[0], ah4[1], ah4[2], ah4[3], addr);
            LDSM4(al4[0], al4[1], al4[2], al4[3], addr + (QL_T - QH_T) * 2);
            #pragma unroll
            for (int nf = 0; nf < 4; nf++) {
                MMA16816(acc[mf][nf], ah4, bhf[nf]);
                MMA16816(acc[mf][nf], ah4, blf[nf]);
                MMA16816(acc[mf][nf], al4, bhf[nf]);
            }
        }
    }

    // ---- register softmax ----
    // scale + per-thread row max (8 values/row), quad-reduce, stash partials
    #pragma unroll
    for (int mf = 0; mf < 4; mf++) {
        float m1 = -1e30f, m2 = -1e30f;
        #pragma unroll
        for (int nf = 0; nf < 4; nf++) {
            acc[mf][nf][0] *= 0.125f; acc[mf][nf][1] *= 0.125f;
            acc[mf][nf][2] *= 0.125f; acc[mf][nf][3] *= 0.125f;
            m1 = fmaxf(m1, fmaxf(acc[mf][nf][0], acc[mf][nf][1]));
            m2 = fmaxf(m2, fmaxf(acc[mf][nf][2], acc[mf][nf][3]));
        }
        m1 = fmaxf(m1, __shfl_xor_sync(0xffffffffu, m1, 1));
        m1 = fmaxf(m1, __shfl_xor_sync(0xffffffffu, m1, 2));
        m2 = fmaxf(m2, __shfl_xor_sync(0xffffffffu, m2, 1));
        m2 = fmaxf(m2, __shfl_xor_sync(0xffffffffu, m2, 2));
        if ((lane & 3) == 0) {
            int r1 = mrow + mf * 16 + (lane >> 2);
            pm[r1 * 4 + cg]       = m1;
            pm[(r1 + 8) * 4 + cg] = m2;
        }
    }
    __syncthreads();

    // exp in place + partial sums
    #pragma unroll
    for (int mf = 0; mf < 4; mf++) {
        int r1 = mrow + mf * 16 + (lane >> 2);
        float4 p1 = *reinterpret_cast<const float4*>(&pm[r1 * 4]);
        float4 p2 = *reinterpret_cast<const float4*>(&pm[(r1 + 8) * 4]);
        float mx1 = fmaxf(fmaxf(p1.x, p1.y), fmaxf(p1.z, p1.w));
        float mx2 = fmaxf(fmaxf(p2.x, p2.y), fmaxf(p2.z, p2.w));
        float s1 = 0.f, s2 = 0.f;
        #pragma unroll
        for (int nf = 0; nf < 4; nf++) {
            float e0 = __expf(acc[mf][nf][0] - mx1);
            float e1 = __expf(acc[mf][nf][1] - mx1);
            float e2 = __expf(acc[mf][nf][2] - mx2);
            float e3 = __expf(acc[mf][nf][3] - mx2);
            acc[mf][nf][0] = e0; acc[mf][nf][1] = e1;
            acc[mf][nf][2] = e2; acc[mf][nf][3] = e3;
            s1 += e0 + e1; s2 += e2 + e3;
        }
        s1 += __shfl_xor_sync(0xffffffffu, s1, 1);
        s1 += __shfl_xor_sync(0xffffffffu, s1, 2);
        s2 += __shfl_xor_sync(0xffffffffu, s2, 1);
        s2 += __shfl_xor_sync(0xffffffffu, s2, 2);
        if ((lane & 3) == 0) {
            ps[r1 * 4 + cg]       = s1;
            ps[(r1 + 8) * 4 + cg] = s2;
        }
    }
    __syncthreads();

    const int s1t[4] = {0, 2, 3, 6};
    const int s2t[4] = {1, 4, 5, 7};
    float* o1 = wout + (size_t)s1t[p]*WSZ;
    float* o2 = wout + (size_t)s2t[p]*WSZ;
    #pragma unroll
    for (int mf = 0; mf < 4; mf++) {
        int r1 = mrow + mf * 16 + (lane >> 2);
        float4 q1 = *reinterpret_cast<const float4*>(&ps[r1 * 4]);
        float4 q2 = *reinterpret_cast<const float4*>(&ps[(r1 + 8) * 4]);
        float inv1 = 1.0f / (q1.x + q1.y + q1.z + q1.w);
        float inv2 = 1.0f / (q2.x + q2.y + q2.z + q2.w);
        size_t base1 = (((size_t)b*NH + h)*NT + r1)*NT;
        size_t base2 = base1 + 8 * NT;
        #pragma unroll
        for (int nf = 0; nf < 4; nf++) {
            int col = ncol + nf * 8 + (lane & 3) * 2;
            float2 w1 = make_float2(acc[mf][nf][0] * inv1, acc[mf][nf][1] * inv1);
            float2 w2 = make_float2(acc[mf][nf][2] * inv2, acc[mf][nf][3] * inv2);
            *reinterpret_cast<float2*>(o1 + base1 + col) = w1;
            *reinterpret_cast<float2*>(o2 + base1 + col) = w1;
            *reinterpret_cast<float2*>(o1 + base2 + col) = w2;
            *reinterpret_cast<float2*>(o2 + base2 + col) = w2;
        }
    }
}

// ======================= K5: attention x V (16 q per block, float4 w) =======================
#define AV_SMEM ((8192*2 + 2048*2) * 4)

__global__ void __launch_bounds__(256, 2) av_kernel(const float* __restrict__ wout) {
    extern __shared__ float smf[];
    float* Vsr = smf;
    float* Vsi = smf + 8192;
    float* sWA = smf + 16384;
    float* sWB = smf + 18432;
    int qt = blockIdx.x, h = blockIdx.y, b = blockIdx.z, tid = threadIdx.x;

    const float* Vr = g_scratch + OFF_VR;
    const float* Vi = g_scratch + OFF_VI;
    for (int l = tid; l < 8192; l += 256) {
        int k = l >> 6, d = l & 63;
        int gi = (b*NT + k)*ND + h*NDH + d;
        Vsr[l] = Vr[gi]; Vsi[l] = Vi[gi];
    }
    for (int l = tid; l < 2048; l += 256) {
        int ql = l >> 7, kk = l & 127;
        int q = qt*16 + ql;
        size_t idx = (((size_t)b*NH + h)*NT + q)*NT + kk;
        sWA[l] = wout[idx] - wout[6*(size_t)WSZ + idx];
        sWB[l] = wout[2*(size_t)WSZ + idx] + wout[3*(size_t)WSZ + idx];
    }
    __syncthreads();

    int d = tid & 63, qi = tid >> 6;
    float ar[4] = {0,0,0,0}, ai[4] = {0,0,0,0};
    for (int kk = 0; kk < 128; kk += 4) {
        float wa4[4][4], wb4[4][4];
        #pragma unroll
        for (int j = 0; j < 4; j++) {
            float4 ta = *reinterpret_cast<const float4*>(&sWA[(qi*4 + j)*128 + kk]);
            float4 tb = *reinterpret_cast<const float4*>(&sWB[(qi*4 + j)*128 + kk]);
            wa4[j][0] = ta.x; wa4[j][1] = ta.y; wa4[j][2] = ta.z; wa4[j][3] = ta.w;
            wb4[j][0] = tb.x; wb4[j][1] = tb.y; wb4[j][2] = tb.z; wb4[j][3] = tb.w;
        }
        #pragma unroll
        for (int u = 0; u < 4; u++) {
            float vr = Vsr[(kk+u)*64 + d], vi = Vsi[(kk+u)*64 + d];
            #pragma unroll
            for (int j = 0; j < 4; j++) {
                ar[j] += wa4[j][u]*vr - wb4[j][u]*vi;
                ai[j] += wb4[j][u]*vr + wa4[j][u]*vi;
            }
        }
    }
    #pragma unroll
    for (int j = 0; j < 4; j++) {
        int q = qt*16 + qi*4 + j;
        size_t go = (size_t)(b*NT + q)*ND + h*NDH + d;
        split_store(g_bf + BF_ARH + go, g_bf + BF_ARL + go, ar[j]);
        split_store(g_bf + BF_AIH + go, g_bf + BF_AIL + go, ai[j]);
    }
}

// ======================= K9: final scalars + layernorm =======================
__global__ void final_kernel(const float* __restrict__ real, const float* __restrict__ imag,
                             const float* __restrict__ W2r, const float* __restrict__ b2r,
                             const float* __restrict__ W2i, const float* __restrict__ b2i,
                             const float* __restrict__ g1,  const float* __restrict__ be1,
                             float* __restrict__ out) {
    int row = blockIdx.x, t = threadIdx.x;
    __shared__ float sbuf[4];
    const float* gre = g_scratch + OFF_GRE + (size_t)row*ND;
    const float* gim = g_scratch + OFF_GIM + (size_t)row*ND;
    const float* re  = real + (size_t)row*ND;
    const float* im  = imag + (size_t)row*ND;

    float grev[3], gimv[3], rev[3], imv[3], w2rv[3], w2iv[3];
    #pragma unroll
    for (int j = 0; j < 3; j++) {
        int d = t + 128*j;
        grev[j] = gre[d]; gimv[j] = gim[d];
        rev[j]  = re[d];  imv[j]  = im[d];
        w2rv[j] = W2r[d]; w2iv[j] = W2i[d];
    }
    float p0=0,p1=0,p2=0,p3=0,p4=0,p5=0;
    #pragma unroll
    for (int j = 0; j < 3; j++) {
        p0 += grev[j]*w2rv[j];
        p1 += gimv[j]*w2iv[j];
        p2 += gimv[j]*w2rv[j];
        p3 += grev[j]*w2iv[j];
        p4 += rev[j]*rev[j] + imv[j]*imv[j];
        p5 -= (rev[j] + imv[j]) * imv[j];
    }
    float d0 = blocksum128(p0, sbuf);
    float d1 = blocksum128(p1, sbuf);
    float d2 = blocksum128(p2, sbuf);
    float d3 = blocksum128(p3, sbuf);
    float d4 = blocksum128(p4, sbuf);   // F_re
    float d5 = blocksum128(p5, sbuf);   // F_im

    float sre  = d0 + b2r[0] - (d1 + b2i[0]);
    float sim  = d2 + b2r[0] + (d3 + b2i[0]);
    float s2   = sre*sre + sim*sim;
    float simn = -(s2*sim) - sim*sim;
    float denom = d4*d4 + d5*d5;
    float Wc = (s2*d4 + simn*d5) / denom;

    float xr[3], xi[3];
    #pragma unroll
    for (int j = 0; j < 3; j++) {
        xr[j] = Wc * (rev[j] - imv[j]);
        xi[j] = 2.0f * Wc * imv[j];
    }
    float mr = blocksum128(xr[0]+xr[1]+xr[2], sbuf) * (1.0f/ND);
    float vrp = 0.f;
    #pragma unroll
    for (int j = 0; j < 3; j++) { float dd = xr[j]-mr; vrp += dd*dd; }
    float vr = blocksum128(vrp, sbuf) * (1.0f/ND);
    float rsr = rsqrtf(vr + 1e-5f);
    float mi = blocksum128(xi[0]+xi[1]+xi[2], sbuf) * (1.0f/ND);
    float vip = 0.f;
    #pragma unroll
    for (int j = 0; j < 3; j++) { float dd = xi[j]-mi; vip += dd*dd; }
    float vi = blocksum128(vip, sbuf) * (1.0f/ND);
    float rsi = rsqrtf(vi + 1e-5f);

    #pragma unroll
    for (int j = 0; j < 3; j++) {
        int d = t + 128*j;
        out[(size_t)row*ND + d]      = (xr[j]-mr)*rsr*g1[d] + be1[d];
        out[CH + (size_t)row*ND + d] = (xi[j]-mi)*rsi*g1[d] + be1[d];
    }
}

// ======================= host launcher =======================
extern "C" void kernel_launch(void* const* d_in, const int* in_sizes, int n_in,
                              void* d_out, int out_size) {
    const float* real  = (const float*)d_in[0];
    const float* imag  = (const float*)d_in[1];
    const float* iproj = (const float*)d_in[2];
    const float* Wq = (const float*)d_in[3];  const float* bq = (const float*)d_in[4];
    const float* Wk = (const float*)d_in[5];  const float* bk = (const float*)d_in[6];
    const float* Wv = (const float*)d_in[7];  const float* bv = (const float*)d_in[8];
    const float* Wo = (const float*)d_in[9];  const float* bo = (const float*)d_in[10];
    const float* W1r = (const float*)d_in[11]; const float* b1r = (const float*)d_in[12];
    const float* W1i = (const float*)d_in[13]; const float* b1i = (const float*)d_in[14];
    const float* W2r = (const float*)d_in[15]; const float* b2r = (const float*)d_in[16];
    const float* W2i = (const float*)d_in[17]; const float* b2i = (const float*)d_in[18];
    const float* g1  = (const float*)d_in[19]; const float* be1 = (const float*)d_in[20];
    float* out = (float*)d_out;

    float* S = nullptr;
    __nv_bfloat16* Bp = nullptr;
    cudaGetSymbolAddress((void**)&S, g_scratch);
    cudaGetSymbolAddress((void**)&Bp, g_bf);

    cudaFuncSetAttribute(scores_mma, cudaFuncAttributeMaxDynamicSharedMemorySize, SC2_SMEM);
    cudaFuncSetAttribute(av_kernel,  cudaFuncAttributeMaxDynamicSharedMemorySize, AV_SMEM);
    cudaFuncSetAttribute(mma_gemm,   cudaFuncAttributeMaxDynamicSharedMemorySize, MMA_SMEM);

    __nv_bfloat16* WH[4]; __nv_bfloat16* WL[4];
    for (int y = 0; y < 4; y++) {
        WH[y] = Bp + BF_W + (size_t)y * 2 * WW;
        WL[y] = WH[y] + WW;
    }
    __nv_bfloat16* CRH = Bp + BF_CATR;            __nv_bfloat16* CRL = CRH + 2*(size_t)WW;
    __nv_bfloat16* CIH = Bp + BF_CATI;            __nv_bfloat16* CIL = CIH + 2*(size_t)WW;

    // 1) fused prep (acts, weights, W1 concats, ih)
    prep_all<<<9616, 256>>>(real, imag, Wq, Wk, Wv, Wo, W1r, W1i, iproj);

    // 2) stage-1: six projection GEMMs (fp32 outputs)
    GemmBatch s1;
    const __nv_bfloat16* AH2[2] = { Bp + BF_RH, Bp + BF_IMH };
    const __nv_bfloat16* AL2[2] = { Bp + BF_RL, Bp + BF_IML };
    const float* biases[3] = { bq, bk, bv };
    size_t outs[6] = { OFF_QR, OFF_QI, OFF_KR, OFF_KI, OFF_VR, OFF_VI };
    for (int o = 0; o < 6; o++) {
        int w = o >> 1, a = o & 1;
        s1.op[o] = { AH2[a], AL2[a], WH[w], WL[w], biases[w], nullptr, 1.0f, 0.f,
                     S + outs[o], nullptr, nullptr, ND, ND, ND, 0 };
    }
    mma_gemm<<<dim3(3, 16, 6), 256, MMA_SMEM>>>(s1);

    // 3) deflate Q/K -> bf16 hi/lo
    ortho_kernel<<<dim3(NM, 4), 128>>>();

    // 4) scores via mma + register softmax -> all 8 weight output sections
    scores_mma<<<dim3(NH, NB, 4), 256, SC2_SMEM>>>(out + 2*(size_t)CH);

    // 5) attention x V -> bf16 hi/lo
    av_kernel<<<dim3(NT/16, NH, NB), 256, AV_SMEM>>>(out + 2*(size_t)CH);

    // 6) stage-2: Wo GEMMs -> A3 [XRE | XIM] (2048 x 768)
    GemmBatch s2;
    s2.op[0] = { Bp + BF_ARH, Bp + BF_ARL, WH[3], WL[3], bo, nullptr, -2.0f, 0.f,
                 nullptr, Bp + BF_A3H, Bp + BF_A3L, ND, ND, A3W, 0 };
    s2.op[1] = { Bp + BF_AIH, Bp + BF_AIL, WH[3], WL[3], bo, nullptr,  2.0f, 0.f,
                 nullptr, Bp + BF_A3H + 384, Bp + BF_A3L + 384, ND, ND, A3W, 0 };
    mma_gemm<<<dim3(3, 16, 2), 256, MMA_SMEM>>>(s2);

    // 7) stage-3: fused W1 complex layer (K=768, both ops read same A3) + bias + GELU
    GemmBatch s3;
    s3.op[0] = { Bp + BF_A3H, Bp + BF_A3L, CRH, CRL, b1r, b1i, 1.0f, -1.0f,
                 S + OFF_GRE, nullptr, nullptr, A3W, A3W, ND, 1 };
    s3.op[1] = { Bp + BF_A3H, Bp + BF_A3L, CIH, CIL, b1r, b1i, 1.0f,  1.0f,
                 S + OFF_GIM, nullptr, nullptr, A3W, A3W, ND, 1 };
    mma_gemm<<<dim3(3, 16, 2), 256, MMA_SMEM>>>(s3);

    // 8) final scalars + layernorm
    final_kernel<<<NM, 128>>>(real, imag, W2r, b2r, W2i, b2i, g1, be1, out);
}

// round 15
// speedup vs baseline: 1.2177x; 1.1293x over previous
#include <cuda_runtime.h>
#include <cuda_bf16.h>
#include <cstdint>
#include <math.h>

#define NB 16
#define NT 128
#define ND 384
#define NH 6
#define NDH 64
#define NM 2048                 // NB*NT

#define CH   786432             // NM*ND
#define WSZ  1572864            // NB*NH*NT*NT
#define WW   147456             // ND*ND
#define A3W  768                // [XRE|XIM] concat width
#define A3SZ 1572864            // 2048*768 = 2*CH

// ---------------- fp32 scratch layout ----------------
#define OFF_IH  0
#define OFF_QR  6144
#define OFF_QI  (OFF_QR + CH)
#define OFF_KR  (OFF_QI + CH)
#define OFF_KI  (OFF_KR + CH)
#define OFF_VR  (OFF_KI + CH)
#define OFF_VI  (OFF_VR + CH)
#define OFF_GRE (OFF_VI + CH)
#define OFF_GIM (OFF_GRE + CH)
#define TOTALF  (OFF_GIM + CH)

// ---------------- bf16 scratch layout ----------------
#define BF_RH   0
#define BF_RL   ((size_t)CH)
#define BF_IMH  ((size_t)2*CH)
#define BF_IML  ((size_t)3*CH)
#define BF_ARH  ((size_t)4*CH)
#define BF_ARL  ((size_t)5*CH)
#define BF_AIH  ((size_t)6*CH)
#define BF_AIL  ((size_t)7*CH)
#define BF_A3H  ((size_t)8*CH)               // 2048 x 768 hi
#define BF_A3L  (BF_A3H + (size_t)A3SZ)      // lo
#define BF_W    (BF_A3L + (size_t)A3SZ)      // 4 weights (Wq,Wk,Wv,Wo) x (hi WW, lo WW)
#define BF_CATR (BF_W + 8*(size_t)WW)        // [W1r|-W1i] 384x768 hi,lo
#define BF_CATI (BF_CATR + 4*(size_t)WW)     // [W1i| W1r] 384x768 hi,lo
#define BF_Q    (BF_CATI + 4*(size_t)WW)     // 4 arrays (QR,QI,KR,KI) x (hi CH, lo CH)
#define TOTB    (BF_Q + 8*(size_t)CH)

__device__ float g_scratch[TOTALF];
__device__ __align__(16) __nv_bfloat16 g_bf[TOTB];

// ======================= helpers =======================
__device__ __forceinline__ uint32_t smem_u32(const void* p) {
    uint32_t a;
    asm("{ .reg .u64 t; cvta.to.shared.u64 t, %1; cvt.u32.u64 %0, t; }" : "=r"(a) : "l"(p));
    return a;
}

__device__ __forceinline__ float blocksum128(float v, float* sbuf) {
    #pragma unroll
    for (int o = 16; o; o >>= 1) v += __shfl_xor_sync(0xffffffffu, v, o);
    if ((threadIdx.x & 31) == 0) sbuf[threadIdx.x >> 5] = v;
    __syncthreads();
    float r = sbuf[0] + sbuf[1] + sbuf[2] + sbuf[3];
    __syncthreads();
    return r;
}
__device__ __forceinline__ float gelu_exact(float x) {
    return 0.5f * x * (1.0f + erff(x * 0.7071067811865475f));
}
__device__ __forceinline__ void split_store(__nv_bfloat16* ph, __nv_bfloat16* pl, float v) {
    __nv_bfloat16 h = __float2bfloat16(v);
    *ph = h;
    *pl = __float2bfloat16(v - __bfloat162float(h));
}

#define LDSM4(r0, r1, r2, r3, a) \
    asm volatile("ldmatrix.sync.aligned.m8n8.x4.shared.b16 {%0,%1,%2,%3}, [%4];" \
                 : "=r"(r0), "=r"(r1), "=r"(r2), "=r"(r3) : "r"(a))

#define LDSM4T(r0, r1, r2, r3, a) \
    asm volatile("ldmatrix.sync.aligned.m8n8.x4.trans.shared.b16 {%0,%1,%2,%3}, [%4];" \
                 : "=r"(r0), "=r"(r1), "=r"(r2), "=r"(r3) : "r"(a))

#define MMA16816(c, a, b) \
    asm volatile("mma.sync.aligned.m16n8k16.row.col.f32.bf16.bf16.f32 " \
                 "{%0,%1,%2,%3}, {%4,%5,%6,%7}, {%8,%9}, {%0,%1,%2,%3};" \
                 : "+f"((c)[0]), "+f"((c)[1]), "+f"((c)[2]), "+f"((c)[3]) \
                 : "r"((a)[0]), "r"((a)[1]), "r"((a)[2]), "r"((a)[3]), \
                   "r"((b)[0]), "r"((b)[1]))

#define CP_ASYNC16(dst, src) \
    asm volatile("cp.async.cg.shared.global [%0], [%1], 16;" :: "r"(dst), "l"(src))
#define CP_COMMIT() asm volatile("cp.async.commit_group;")
#define CP_WAIT1()  asm volatile("cp.async.wait_group 1;")
#define CP_WAIT0()  asm volatile("cp.async.wait_group 0;")

// ======================= mma.sync batched GEMM =======================
struct GemmOp {
    const __nv_bfloat16 *ah, *al, *bh, *bl;
    const float *bias, *bias2; float bscale, bscale2;
    float* out;
    __nv_bfloat16 *outh, *outl;
    int K, lda, ldo, gelu;
};
struct GemmBatch { GemmOp op[6]; };

#define SMS 40
#define MAT_ELE (128 * SMS)           // 5120
#define STG_ELE (4 * MAT_ELE)         // 20480
#define MMA_SMEM (2 * STG_ELE * 2)    // 81920 B

__global__ void __launch_bounds__(256, 2) mma_gemm(GemmBatch batch) {
    extern __shared__ __nv_bfloat16 sm[];
    uint32_t smb = smem_u32(sm);
    const GemmOp op = batch.op[blockIdx.z];
    const int tid = threadIdx.x, lane = tid & 31, warp = tid >> 5;
    const int m0 = blockIdx.y * 128, n0 = blockIdx.x * 128;
    const int m0w = (warp & 1) * 64, n0w = (warp >> 1) * 32;
    const int Kd = op.K, lda = op.lda;
    const int nchunks = Kd >> 5;

    const int aBase = (m0w + (lane & 15)) * SMS + (lane >> 4) * 8;
    const int bBase = (n0w + ((lane >> 4) & 1) * 8 + (lane & 7)) * SMS + ((lane >> 3) & 1) * 8;

    float acc[4][4][4];
    #pragma unroll
    for (int i = 0; i < 4; i++)
        #pragma unroll
        for (int j = 0; j < 4; j++)
            #pragma unroll
            for (int q = 0; q < 4; q++) acc[i][j][q] = 0.f;

    auto load_stage = [&](int c, int s) {
        int kc = c * 32;
        #pragma unroll
        for (int mat = 0; mat < 4; mat++) {
            const __nv_bfloat16* src = (mat == 0) ? op.ah : (mat == 1) ? op.al
                                     : (mat == 2) ? op.bh : op.bl;
            int rb = (mat < 2) ? m0 : n0;
            int stride = (mat < 2) ? lda : Kd;
            #pragma unroll
            for (int i = 0; i < 2; i++) {
                int l = tid + 256 * i;
                int row = l >> 2, c8 = l & 3;
                const __nv_bfloat16* g = src + (size_t)(rb + row) * stride + kc + c8 * 8;
                uint32_t d = smb + (uint32_t)(s * STG_ELE + mat * MAT_ELE + row * SMS + c8 * 8) * 2;
                CP_ASYNC16(d, g);
            }
        }
        CP_COMMIT();
    };

    load_stage(0, 0);

    for (int c = 0; c < nchunks; c++) {
        if (c + 1 < nchunks) { load_stage(c + 1, (c + 1) & 1); CP_WAIT1(); }
        else                 { CP_WAIT0(); }
        __syncthreads();

        uint32_t stb = smb + (uint32_t)((c & 1) * STG_ELE) * 2;
        #pragma unroll
        for (int ks = 0; ks < 2; ks++) {
            uint32_t bhf[4][2], blf[4][2];
            #pragma unroll
            for (int pr = 0; pr < 2; pr++) {
                uint32_t addr = stb + (uint32_t)(2 * MAT_ELE + bBase + pr * 16 * SMS + ks * 16) * 2;
                uint32_t r0, r1, r2, r3;
                LDSM4(r0, r1, r2, r3, addr);
                bhf[2*pr][0] = r0; bhf[2*pr][1] = r1;
                bhf[2*pr+1][0] = r2; bhf[2*pr+1][1] = r3;
                LDSM4(r0, r1, r2, r3, addr + MAT_ELE * 2);
                blf[2*pr][0] = r0; blf[2*pr][1] = r1;
                blf[2*pr+1][0] = r2; blf[2*pr+1][1] = r3;
            }
            #pragma unroll
            for (int mf = 0; mf < 4; mf++) {
                uint32_t ah4[4], al4[4];
                uint32_t addr = stb + (uint32_t)(aBase + mf * 16 * SMS + ks * 16) * 2;
                LDSM4(ah4[0], ah4[1], ah4[2], ah4[3], addr);
                LDSM4(al4[0], al4[1], al4[2], al4[3], addr + MAT_ELE * 2);
                #pragma unroll
                for (int nf = 0; nf < 4; nf++) {
                    MMA16816(acc[mf][nf], ah4, bhf[nf]);
                    MMA16816(acc[mf][nf], ah4, blf[nf]);
                    MMA16816(acc[mf][nf], al4, bhf[nf]);
                }
            }
        }
        __syncthreads();
    }

    #pragma unroll
    for (int mf = 0; mf < 4; mf++) {
        #pragma unroll
        for (int nf = 0; nf < 4; nf++) {
            int r0 = m0 + m0w + mf * 16 + (lane >> 2);
            int col = n0 + n0w + nf * 8 + (lane & 3) * 2;
            float v0 = acc[mf][nf][0], v1 = acc[mf][nf][1];
            float v2 = acc[mf][nf][2], v3 = acc[mf][nf][3];
            if (op.bias) {
                float bb0 = op.bscale * op.bias[col], bb1 = op.bscale * op.bias[col + 1];
                v0 += bb0; v1 += bb1; v2 += bb0; v3 += bb1;
            }
            if (op.bias2) {
                float bb0 = op.bscale2 * op.bias2[col], bb1 = op.bscale2 * op.bias2[col + 1];
                v0 += bb0; v1 += bb1; v2 += bb0; v3 += bb1;
            }
            if (op.gelu) {
                v0 = gelu_exact(v0); v1 = gelu_exact(v1);
                v2 = gelu_exact(v2); v3 = gelu_exact(v3);
            }
            if (op.out) {
                *reinterpret_cast<float2*>(op.out + (size_t)r0 * op.ldo + col)       = make_float2(v0, v1);
                *reinterpret_cast<float2*>(op.out + (size_t)(r0 + 8) * op.ldo + col) = make_float2(v2, v3);
            }
            if (op.outh) {
                __nv_bfloat16 h0 = __float2bfloat16(v0), h1 = __float2bfloat16(v1);
                __nv_bfloat16 h2 = __float2bfloat16(v2), h3 = __float2bfloat16(v3);
                __nv_bfloat162 hp0; hp0.x = h0; hp0.y = h1;
                __nv_bfloat162 hp1; hp1.x = h2; hp1.y = h3;
                __nv_bfloat162 lp0; lp0.x = __float2bfloat16(v0 - __bfloat162float(h0));
                                    lp0.y = __float2bfloat16(v1 - __bfloat162float(h1));
                __nv_bfloat162 lp1; lp1.x = __float2bfloat16(v2 - __bfloat162float(h2));
                                    lp1.y = __float2bfloat16(v3 - __bfloat162float(h3));
                size_t i0 = (size_t)r0 * op.ldo + col, i1 = (size_t)(r0 + 8) * op.ldo + col;
                *reinterpret_cast<__nv_bfloat162*>(op.outh + i0) = hp0;
                *reinterpret_cast<__nv_bfloat162*>(op.outh + i1) = hp1;
                *reinterpret_cast<__nv_bfloat162*>(op.outl + i0) = lp0;
                *reinterpret_cast<__nv_bfloat162*>(op.outl + i1) = lp1;
            }
        }
    }
}

// ======================= fused prep kernel (+ih) =======================
__global__ void prep_all(const float* __restrict__ real, const float* __restrict__ imag,
                         const float* __restrict__ Wq, const float* __restrict__ Wk,
                         const float* __restrict__ Wv, const float* __restrict__ Wo,
                         const float* __restrict__ W1r, const float* __restrict__ W1i,
                         const float* __restrict__ iproj) {
    int bid = blockIdx.x, tid = threadIdx.x;
    if (bid < 6144) {
        int y = bid / 3072;
        int i = (bid - y * 3072) * 256 + tid;
        const float* s = y ? imag : real;
        size_t o = y ? BF_IMH : BF_RH;
        split_store(g_bf + o + i, g_bf + o + CH + i, s[i]);
    } else if (bid < 8448) {
        int t = bid - 6144;
        int y = t / 576;
        int i = (t - y * 576) * 256 + tid;
        const float* ws = (y == 0) ? Wq : (y == 1) ? Wk : (y == 2) ? Wv : Wo;
        size_t base = BF_W + (size_t)y * 2 * WW;
        split_store(g_bf + base + i, g_bf + base + WW + i, ws[i]);
    } else if (bid < 9600) {
        int i = (bid - 8448) * 256 + tid;
        int n = i / 768, k = i % 768;
        float vr = (k < 384) ? W1r[n*384 + k] : -W1i[n*384 + (k-384)];
        float vi = (k < 384) ? W1i[n*384 + k] :  W1r[n*384 + (k-384)];
        split_store(g_bf + BF_CATR + i, g_bf + BF_CATR + 2*(size_t)WW + i, vr);
        split_store(g_bf + BF_CATI + i, g_bf + BF_CATI + 2*(size_t)WW + i, vi);
    } else {
        int b = bid - 9600;
        __shared__ float sred[8];
        __shared__ float sn3;
        if (tid == 0) {
            float a = iproj[b*128+0], c = iproj[b*128+1], d = iproj[b*128+2];
            sn3 = sqrtf(a*a + c*c + d*d);
        }
        __syncthreads();
        float w = (tid < 128) ? (iproj[b*128 + tid] / sn3) : 0.f;
        float p = w * w;
        #pragma unroll
        for (int o = 16; o; o >>= 1) p += __shfl_xor_sync(0xffffffffu, p, o);
        if ((tid & 31) == 0) sred[tid >> 5] = p;
        __syncthreads();
        float sum = 0.f;
        #pragma unroll
        for (int ww = 0; ww < 8; ww++) sum += sred[ww];
        float nf = sqrtf(3.0f * sum);
        if (tid < 128) {
            float val = w / nf;
            float* ih = g_scratch + OFF_IH + b*ND;
            ih[tid] = val; ih[tid+128] = val; ih[tid+256] = val;
        }
    }
}

// ======================= K3: deflation -> bf16 hi/lo =======================
__global__ void ortho_kernel() {
    __shared__ float sbuf[4];
    int y = blockIdx.y;
    const float* arr = g_scratch + OFF_QR + (size_t)y * CH;
    __nv_bfloat16* oh = g_bf + BF_Q + (size_t)y * 2 * CH;
    __nv_bfloat16* ol = oh + CH;
    int row = blockIdx.x, t = threadIdx.x, b = row >> 7;
    const float* ih = g_scratch + OFF_IH + b*ND;
    float q0 = arr[row*ND + t], q1 = arr[row*ND + t + 128], q2 = arr[row*ND + t + 256];
    float i0 = ih[t], i1 = ih[t+128], i2 = ih[t+256];
    float dot = blocksum128(q0*i0 + q1*i1 + q2*i2, sbuf);
    split_store(oh + (size_t)row*ND + t,       ol + (size_t)row*ND + t,       q0 - dot*i0);
    split_store(oh + (size_t)row*ND + t + 128, ol + (size_t)row*ND + t + 128, q1 - dot*i1);
    split_store(oh + (size_t)row*ND + t + 256, ol + (size_t)row*ND + t + 256, q2 - dot*i2);
}

// ======================= K4: scores via mma.sync, register softmax =======================
#define QH_T 0
#define QL_T 9216
#define KH_T 18432
#define KL_T 27648
#define SC2_SMEM (73728 + 4096)

__global__ void __launch_bounds__(256, 2) scores_mma(float* __restrict__ wout) {
    extern __shared__ char smraw[];
    __nv_bfloat16* smb16 = reinterpret_cast<__nv_bfloat16*>(smraw);
    float* pm = reinterpret_cast<float*>(smraw + 73728);
    float* ps = pm + 512;
    uint32_t smb = smem_u32(smraw);
    int h = blockIdx.x, b = blockIdx.y, p = blockIdx.z, tid = threadIdx.x;
    int lane = tid & 31, warp = tid >> 5;

    const __nv_bfloat16* Qbase = g_bf + BF_Q + (size_t)(((p >> 1) & 1) * 2) * CH;
    const __nv_bfloat16* Kbase = g_bf + BF_Q + (size_t)((2 + (p & 1)) * 2) * CH;

    #pragma unroll
    for (int i = 0; i < 16; i++) {
        int l = tid + 256 * i;
        int mat = l >> 10, v = l & 1023;
        int row = v >> 3, col = (v & 7) * 8;
        const __nv_bfloat16* src = (mat == 0) ? Qbase : (mat == 1) ? Qbase + CH
                                  : (mat == 2) ? Kbase : Kbase + CH;
        const __nv_bfloat16* g = src + (size_t)(b*NT + row) * ND + h*NDH + col;
        uint32_t d = smb + (uint32_t)(mat * 9216 + row * 72 + col) * 2;
        CP_ASYNC16(d, g);
    }
    CP_COMMIT();
    CP_WAIT0();
    __syncthreads();

    const int mrow = (warp & 1) * 64, ncol = (warp >> 1) * 32;
    const int cg = warp >> 1;
    const int aBase = (mrow + (lane & 15)) * 72 + (lane >> 4) * 8;
    const int bBase = (ncol + ((lane >> 4) & 1) * 8 + (lane & 7)) * 72 + ((lane >> 3) & 1) * 8;

    float acc[4][4][4];
    #pragma unroll
    for (int i = 0; i < 4; i++)
        #pragma unroll
        for (int j = 0; j < 4; j++)
            #pragma unroll
            for (int q = 0; q < 4; q++) acc[i][j][q] = 0.f;

    #pragma unroll
    for (int ks = 0; ks < 4; ks++) {
        uint32_t bhf[4][2], blf[4][2];
        #pragma unroll
        for (int pr = 0; pr < 2; pr++) {
            uint32_t addr = smb + (uint32_t)(KH_T + bBase + pr * 16 * 72 + ks * 16) * 2;
            uint32_t r0, r1, r2, r3;
            LDSM4(r0, r1, r2, r3, addr);
            bhf[2*pr][0] = r0; bhf[2*pr][1] = r1;
            bhf[2*pr+1][0] = r2; bhf[2*pr+1][1] = r3;
            LDSM4(r0, r1, r2, r3, addr + (KL_T - KH_T) * 2);
            blf[2*pr][0] = r0; blf[2*pr][1] = r1;
            blf[2*pr+1][0] = r2; blf[2*pr+1][1] = r3;
        }
        #pragma unroll
        for (int mf = 0; mf < 4; mf++) {
            uint32_t ah4[4], al4[4];
            uint32_t addr = smb + (uint32_t)(QH_T + aBase + mf * 16 * 72 + ks * 16) * 2;
            LDSM4(ah4[0], ah4[1], ah4[2], ah4[3], addr);
            LDSM4(al4[0], al4[1], al4[2], al4[3], addr + (QL_T - QH_T) * 2);
            #pragma unroll
            for (int nf = 0; nf < 4; nf++) {
                MMA16816(acc[mf][nf], ah4, bhf[nf]);
                MMA16816(acc[mf][nf], ah4, blf[nf]);
                MMA16816(acc[mf][nf], al4, bhf[nf]);
            }
        }
    }

    #pragma unroll
    for (int mf = 0; mf < 4; mf++) {
        float m1 = -1e30f, m2 = -1e30f;
        #pragma unroll
        for (int nf = 0; nf < 4; nf++) {
            acc[mf][nf][0] *= 0.125f; acc[mf][nf][1] *= 0.125f;
            acc[mf][nf][2] *= 0.125f; acc[mf][nf][3] *= 0.125f;
            m1 = fmaxf(m1, fmaxf(acc[mf][nf][0], acc[mf][nf][1]));
            m2 = fmaxf(m2, fmaxf(acc[mf][nf][2], acc[mf][nf][3]));
        }
        m1 = fmaxf(m1, __shfl_xor_sync(0xffffffffu, m1, 1));
        m1 = fmaxf(m1, __shfl_xor_sync(0xffffffffu, m1, 2));
        m2 = fmaxf(m2, __shfl_xor_sync(0xffffffffu, m2, 1));
        m2 = fmaxf(m2, __shfl_xor_sync(0xffffffffu, m2, 2));
        if ((lane & 3) == 0) {
            int r1 = mrow + mf * 16 + (lane >> 2);
            pm[r1 * 4 + cg]       = m1;
            pm[(r1 + 8) * 4 + cg] = m2;
        }
    }
    __syncthreads();

    #pragma unroll
    for (int mf = 0; mf < 4; mf++) {
        int r1 = mrow + mf * 16 + (lane >> 2);
        float4 p1 = *reinterpret_cast<const float4*>(&pm[r1 * 4]);
        float4 p2 = *reinterpret_cast<const float4*>(&pm[(r1 + 8) * 4]);
        float mx1 = fmaxf(fmaxf(p1.x, p1.y), fmaxf(p1.z, p1.w));
        float mx2 = fmaxf(fmaxf(p2.x, p2.y), fmaxf(p2.z, p2.w));
        float s1 = 0.f, s2 = 0.f;
        #pragma unroll
        for (int nf = 0; nf < 4; nf++) {
            float e0 = __expf(acc[mf][nf][0] - mx1);
            float e1 = __expf(acc[mf][nf][1] - mx1);
            float e2 = __expf(acc[mf][nf][2] - mx2);
            float e3 = __expf(acc[mf][nf][3] - mx2);
            acc[mf][nf][0] = e0; acc[mf][nf][1] = e1;
            acc[mf][nf][2] = e2; acc[mf][nf][3] = e3;
            s1 += e0 + e1; s2 += e2 + e3;
        }
        s1 += __shfl_xor_sync(0xffffffffu, s1, 1);
        s1 += __shfl_xor_sync(0xffffffffu, s1, 2);
        s2 += __shfl_xor_sync(0xffffffffu, s2, 1);
        s2 += __shfl_xor_sync(0xffffffffu, s2, 2);
        if ((lane & 3) == 0) {
            ps[r1 * 4 + cg]       = s1;
            ps[(r1 + 8) * 4 + cg] = s2;
        }
    }
    __syncthreads();

    const int s1t[4] = {0, 2, 3, 6};
    const int s2t[4] = {1, 4, 5, 7};
    float* o1 = wout + (size_t)s1t[p]*WSZ;
    float* o2 = wout + (size_t)s2t[p]*WSZ;
    #pragma unroll
    for (int mf = 0; mf < 4; mf++) {
        int r1 = mrow + mf * 16 + (lane >> 2);
        float4 q1 = *reinterpret_cast<const float4*>(&ps[r1 * 4]);
        float4 q2 = *reinterpret_cast<const float4*>(&ps[(r1 + 8) * 4]);
        float inv1 = 1.0f / (q1.x + q1.y + q1.z + q1.w);
        float inv2 = 1.0f / (q2.x + q2.y + q2.z + q2.w);
        size_t base1 = (((size_t)b*NH + h)*NT + r1)*NT;
        size_t base2 = base1 + 8 * NT;
        #pragma unroll
        for (int nf = 0; nf < 4; nf++) {
            int col = ncol + nf * 8 + (lane & 3) * 2;
            float2 w1 = make_float2(acc[mf][nf][0] * inv1, acc[mf][nf][1] * inv1);
            float2 w2 = make_float2(acc[mf][nf][2] * inv2, acc[mf][nf][3] * inv2);
            *reinterpret_cast<float2*>(o1 + base1 + col) = w1;
            *reinterpret_cast<float2*>(o2 + base1 + col) = w1;
            *reinterpret_cast<float2*>(o1 + base2 + col) = w2;
            *reinterpret_cast<float2*>(o2 + base2 + col) = w2;
        }
    }
}

// ======================= K5: attention x V via mma.sync =======================
// smem (bf16 elems): wA_h 0, wA_l 8704, wBn_h 17408, wBn_l 26112 (64x136 each)
//   VR_H 34816, VR_L 44032, VI_H 53248, VI_L 62464, VIN_H 71680, VIN_L 80896 (128x72 each)
#define AVW 136
#define AVV 72
#define AVM_SMEM (90112 * 2)   // 180224 B

__global__ void __launch_bounds__(256) av_mma(const float* __restrict__ wout) {
    extern __shared__ __nv_bfloat16 smav[];
    uint32_t smb = smem_u32(smav);
    int qt = blockIdx.x, h = blockIdx.y, b = blockIdx.z, tid = threadIdx.x;
    int lane = tid & 31, warp = tid >> 5;

    // load w sections -> wA, wBn (bf16 hi/lo)
    for (int i = tid; i < 8192; i += 256) {
        int q = i >> 7, k = i & 127;
        size_t idx = (((size_t)b*NH + h)*NT + qt*64 + q)*NT + k;
        float w0 = wout[idx];
        float w6 = wout[6*(size_t)WSZ + idx];
        float w2 = wout[2*(size_t)WSZ + idx];
        float w3 = wout[3*(size_t)WSZ + idx];
        float wa  = w0 - w6;
        float wbn = -(w2 + w3);
        int off = q * AVW + k;
        split_store(smav + off,         smav + 8704  + off, wa);
        split_store(smav + 17408 + off, smav + 26112 + off, wbn);
    }
    // load V -> Vr, Vi, Vin (bf16 hi/lo), layout [k][d] pad 72
    const float* Vr = g_scratch + OFF_VR;
    const float* Vi = g_scratch + OFF_VI;
    for (int i = tid; i < 8192; i += 256) {
        int k = i >> 6, d = i & 63;
        int gi = (b*NT + k)*ND + h*NDH + d;
        int off = k * AVV + d;
        split_store(smav + 34816 + off, smav + 44032 + off, Vr[gi]);
        float vi = Vi[gi];
        __nv_bfloat16 vih = __float2bfloat16(vi);
        __nv_bfloat16 vil = __float2bfloat16(vi - __bfloat162float(vih));
        smav[53248 + off] = vih;           smav[62464 + off] = vil;
        smav[71680 + off] = __hneg(vih);   smav[80896 + off] = __hneg(vil);
    }
    __syncthreads();

    const int m0w = (warp & 1) * 32, d0 = (warp >> 1) * 16;
    const int aBase = (m0w + (lane & 15)) * AVW + (lane >> 4) * 8;
    // trans B address: rows = k (16), col = d
    const int bOff = (lane & 15) * AVV + d0 + (lane >> 4) * 8;

    float accR[2][2][4], accI[2][2][4];
    #pragma unroll
    for (int i = 0; i < 2; i++)
        #pragma unroll
        for (int j = 0; j < 2; j++)
            #pragma unroll
            for (int q = 0; q < 4; q++) { accR[i][j][q] = 0.f; accI[i][j][q] = 0.f; }

    #pragma unroll
    for (int ks = 0; ks < 8; ks++) {
        // B frags (trans): 6 mats, each -> 2 n-frags (d0..7, d8..15)
        uint32_t vrh[2][2], vrl[2][2], vih[2][2], vil[2][2], vnh[2][2], vnl[2][2];
        {
            uint32_t base = smb + (uint32_t)(34816 + ks*16*AVV + bOff) * 2;
            uint32_t r0,r1,r2,r3;
            LDSM4T(r0,r1,r2,r3, base);
            vrh[0][0]=r0; vrh[0][1]=r1; vrh[1][0]=r2; vrh[1][1]=r3;
            LDSM4T(r0,r1,r2,r3, base + 9216*2);
            vrl[0][0]=r0; vrl[0][1]=r1; vrl[1][0]=r2; vrl[1][1]=r3;
            LDSM4T(r0,r1,r2,r3, base + 18432*2);
            vih[0][0]=r0; vih[0][1]=r1; vih[1][0]=r2; vih[1][1]=r3;
            LDSM4T(r0,r1,r2,r3, base + 27648*2);
            vil[0][0]=r0; vil[0][1]=r1; vil[1][0]=r2; vil[1][1]=r3;
            LDSM4T(r0,r1,r2,r3, base + 36864*2);
            vnh[0][0]=r0; vnh[0][1]=r1; vnh[1][0]=r2; vnh[1][1]=r3;
            LDSM4T(r0,r1,r2,r3, base + 46080*2);
            vnl[0][0]=r0; vnl[0][1]=r1; vnl[1][0]=r2; vnl[1][1]=r3;
        }
        #pragma unroll
        for (int mf = 0; mf < 2; mf++) {
            uint32_t wah[4], wal[4], wbh[4], wbl[4];
            uint32_t addr = smb + (uint32_t)(aBase + mf*16*AVW + ks*16) * 2;
            LDSM4(wah[0], wah[1], wah[2], wah[3], addr);
            LDSM4(wal[0], wal[1], wal[2], wal[3], addr + 8704*2);
            LDSM4(wbh[0], wbh[1], wbh[2], wbh[3], addr + 17408*2);
            LDSM4(wbl[0], wbl[1], wbl[2], wbl[3], addr + 26112*2);
            #pragma unroll
            for (int nf = 0; nf < 2; nf++) {
                // Ar = wA@Vr + wBn@Vi
                MMA16816(accR[mf][nf], wah, vrh[nf]);
                MMA16816(accR[mf][nf], wah, vrl[nf]);
                MMA16816(accR[mf][nf], wal, vrh[nf]);
                MMA16816(accR[mf][nf], wbh, vih[nf]);
                MMA16816(accR[mf][nf], wbh, vil[nf]);
                MMA16816(accR[mf][nf], wbl, vih[nf]);
                // -Ai = wBn@Vr + wA@Vin
                MMA16816(accI[mf][nf], wbh, vrh[nf]);
                MMA16816(accI[mf][nf], wbh, vrl[nf]);
                MMA16816(accI[mf][nf], wbl, vrh[nf]);
                MMA16816(accI[mf][nf], wah, vnh[nf]);
                MMA16816(accI[mf][nf], wah, vnl[nf]);
                MMA16816(accI[mf][nf], wal, vnh[nf]);
            }
        }
    }

    // epilogue: Ar = accR, Ai = -accI
    #pragma unroll
    for (int mf = 0; mf < 2; mf++) {
        #pragma unroll
        for (int nf = 0; nf < 2; nf++) {
            int r = m0w + mf * 16 + (lane >> 2);
            int d = d0 + nf * 8 + (lane & 3) * 2;
            int q = qt * 64 + r;
            size_t go0 = (size_t)(b*NT + q) * ND + h*NDH + d;
            size_t go1 = go0 + (size_t)8 * ND;
            split_store(g_bf + BF_ARH + go0,     g_bf + BF_ARL + go0,     accR[mf][nf][0]);
            split_store(g_bf + BF_ARH + go0 + 1, g_bf + BF_ARL + go0 + 1, accR[mf][nf][1]);
            split_store(g_bf + BF_ARH + go1,     g_bf + BF_ARL + go1,     accR[mf][nf][2]);
            split_store(g_bf + BF_ARH + go1 + 1, g_bf + BF_ARL + go1 + 1, accR[mf][nf][3]);
            split_store(g_bf + BF_AIH + go0,     g_bf + BF_AIL + go0,     -accI[mf][nf][0]);
            split_store(g_bf + BF_AIH + go0 + 1, g_bf + BF_AIL + go0 + 1, -accI[mf][nf][1]);
            split_store(g_bf + BF_AIH + go1,     g_bf + BF_AIL + go1,     -accI[mf][nf][2]);
            split_store(g_bf + BF_AIH + go1 + 1, g_bf + BF_AIL + go1 + 1, -accI[mf][nf][3]);
        }
    }
}

// ======================= K9: final scalars + layernorm =======================
__global__ void final_kernel(const float* __restrict__ real, const float* __restrict__ imag,
                             const float* __restrict__ W2r, const float* __restrict__ b2r,
                             const float* __restrict__ W2i, const float* __restrict__ b2i,
                             const float* __restrict__ g1,  const float* __restrict__ be1,
                             float* __restrict__ out) {
    int row = blockIdx.x, t = threadIdx.x;
    __shared__ float sbuf[4];
    const float* gre = g_scratch + OFF_GRE + (size_t)row*ND;
    const float* gim = g_scratch + OFF_GIM + (size_t)row*ND;
    const float* re  = real + (size_t)row*ND;
    const float* im  = imag + (size_t)row*ND;

    float grev[3], gimv[3], rev[3], imv[3], w2rv[3], w2iv[3];
    #pragma unroll
    for (int j = 0; j < 3; j++) {
        int d = t + 128*j;
        grev[j] = gre[d]; gimv[j] = gim[d];
        rev[j]  = re[d];  imv[j]  = im[d];
        w2rv[j] = W2r[d]; w2iv[j] = W2i[d];
    }
    float p0=0,p1=0,p2=0,p3=0,p4=0,p5=0;
    #pragma unroll
    for (int j = 0; j < 3; j++) {
        p0 += grev[j]*w2rv[j];
        p1 += gimv[j]*w2iv[j];
        p2 += gimv[j]*w2rv[j];
        p3 += grev[j]*w2iv[j];
        p4 += rev[j]*rev[j] + imv[j]*imv[j];
        p5 -= (rev[j] + imv[j]) * imv[j];
    }
    float d0 = blocksum128(p0, sbuf);
    float d1 = blocksum128(p1, sbuf);
    float d2 = blocksum128(p2, sbuf);
    float d3 = blocksum128(p3, sbuf);
    float d4 = blocksum128(p4, sbuf);
    float d5 = blocksum128(p5, sbuf);

    float sre  = d0 + b2r[0] - (d1 + b2i[0]);
    float sim  = d2 + b2r[0] + (d3 + b2i[0]);
    float s2   = sre*sre + sim*sim;
    float simn = -(s2*sim) - sim*sim;
    float denom = d4*d4 + d5*d5;
    float Wc = (s2*d4 + simn*d5) / denom;

    float xr[3], xi[3];
    #pragma unroll
    for (int j = 0; j < 3; j++) {
        xr[j] = Wc * (rev[j] - imv[j]);
        xi[j] = 2.0f * Wc * imv[j];
    }
    float mr = blocksum128(xr[0]+xr[1]+xr[2], sbuf) * (1.0f/ND);
    float vrp = 0.f;
    #pragma unroll
    for (int j = 0; j < 3; j++) { float dd = xr[j]-mr; vrp += dd*dd; }
    float vr = blocksum128(vrp, sbuf) * (1.0f/ND);
    float rsr = rsqrtf(vr + 1e-5f);
    float mi = blocksum128(xi[0]+xi[1]+xi[2], sbuf) * (1.0f/ND);
    float vip = 0.f;
    #pragma unroll
    for (int j = 0; j < 3; j++) { float dd = xi[j]-mi; vip += dd*dd; }
    float vi = blocksum128(vip, sbuf) * (1.0f/ND);
    float rsi = rsqrtf(vi + 1e-5f);

    #pragma unroll
    for (int j = 0; j < 3; j++) {
        int d = t + 128*j;
        out[(size_t)row*ND + d]      = (xr[j]-mr)*rsr*g1[d] + be1[d];
        out[CH + (size_t)row*ND + d] = (xi[j]-mi)*rsi*g1[d] + be1[d];
    }
}

// ======================= host launcher =======================
extern "C" void kernel_launch(void* const* d_in, const int* in_sizes, int n_in,
                              void* d_out, int out_size) {
    const float* real  = (const float*)d_in[0];
    const float* imag  = (const float*)d_in[1];
    const float* iproj = (const float*)d_in[2];
    const float* Wq = (const float*)d_in[3];  const float* bq = (const float*)d_in[4];
    const float* Wk = (const float*)d_in[5];  const float* bk = (const float*)d_in[6];
    const float* Wv = (const float*)d_in[7];  const float* bv = (const float*)d_in[8];
    const float* Wo = (const float*)d_in[9];  const float* bo = (const float*)d_in[10];
    const float* W1r = (const float*)d_in[11]; const float* b1r = (const float*)d_in[12];
    const float* W1i = (const float*)d_in[13]; const float* b1i = (const float*)d_in[14];
    const float* W2r = (const float*)d_in[15]; const float* b2r = (const float*)d_in[16];
    const float* W2i = (const float*)d_in[17]; const float* b2i = (const float*)d_in[18];
    const float* g1  = (const float*)d_in[19]; const float* be1 = (const float*)d_in[20];
    float* out = (float*)d_out;

    float* S = nullptr;
    __nv_bfloat16* Bp = nullptr;
    cudaGetSymbolAddress((void**)&S, g_scratch);
    cudaGetSymbolAddress((void**)&Bp, g_bf);

    cudaFuncSetAttribute(scores_mma, cudaFuncAttributeMaxDynamicSharedMemorySize, SC2_SMEM);
    cudaFuncSetAttribute(av_mma,     cudaFuncAttributeMaxDynamicSharedMemorySize, AVM_SMEM);
    cudaFuncSetAttribute(mma_gemm,   cudaFuncAttributeMaxDynamicSharedMemorySize, MMA_SMEM);

    __nv_bfloat16* WH[4]; __nv_bfloat16* WL[4];
    for (int y = 0; y < 4; y++) {
        WH[y] = Bp + BF_W + (size_t)y * 2 * WW;
        WL[y] = WH[y] + WW;
    }
    __nv_bfloat16* CRH = Bp + BF_CATR;            __nv_bfloat16* CRL = CRH + 2*(size_t)WW;
    __nv_bfloat16* CIH = Bp + BF_CATI;            __nv_bfloat16* CIL = CIH + 2*(size_t)WW;

    // 1) fused prep
    prep_all<<<9616, 256>>>(real, imag, Wq, Wk, Wv, Wo, W1r, W1i, iproj);

    // 2) stage-1: six projection GEMMs
    GemmBatch s1;
    const __nv_bfloat16* AH2[2] = { Bp + BF_RH, Bp + BF_IMH };
    const __nv_bfloat16* AL2[2] = { Bp + BF_RL, Bp + BF_IML };
    const float* biases[3] = { bq, bk, bv };
    size_t outs[6] = { OFF_QR, OFF_QI, OFF_KR, OFF_KI, OFF_VR, OFF_VI };
    for (int o = 0; o < 6; o++) {
        int w = o >> 1, a = o & 1;
        s1.op[o] = { AH2[a], AL2[a], WH[w], WL[w], biases[w], nullptr, 1.0f, 0.f,
                     S + outs[o], nullptr, nullptr, ND, ND, ND, 0 };
    }
    mma_gemm<<<dim3(3, 16, 6), 256, MMA_SMEM>>>(s1);

    // 3) deflate Q/K -> bf16 hi/lo
    ortho_kernel<<<dim3(NM, 4), 128>>>();

    // 4) scores via mma + register softmax
    scores_mma<<<dim3(NH, NB, 4), 256, SC2_SMEM>>>(out + 2*(size_t)CH);

    // 5) attention x V via mma
    av_mma<<<dim3(2, NH, NB), 256, AVM_SMEM>>>(out + 2*(size_t)CH);

    // 6) stage-2: Wo GEMMs -> A3 [XRE | XIM]
    GemmBatch s2;
    s2.op[0] = { Bp + BF_ARH, Bp + BF_ARL, WH[3], WL[3], bo, nullptr, -2.0f, 0.f,
                 nullptr, Bp + BF_A3H, Bp + BF_A3L, ND, ND, A3W, 0 };
    s2.op[1] = { Bp + BF_AIH, Bp + BF_AIL, WH[3], WL[3], bo, nullptr,  2.0f, 0.f,
                 nullptr, Bp + BF_A3H + 384, Bp + BF_A3L + 384, ND, ND, A3W, 0 };
    mma_gemm<<<dim3(3, 16, 2), 256, MMA_SMEM>>>(s2);

    // 7) stage-3: fused W1 complex layer + bias + GELU
    GemmBatch s3;
    s3.op[0] = { Bp + BF_A3H, Bp + BF_A3L, CRH, CRL, b1r, b1i, 1.0f, -1.0f,
                 S + OFF_GRE, nullptr, nullptr, A3W, A3W, ND, 1 };
    s3.op[1] = { Bp + BF_A3H, Bp + BF_A3L, CIH, CIL, b1r, b1i, 1.0f,  1.0f,
                 S + OFF_GIM, nullptr, nullptr, A3W, A3W, ND, 1 };
    mma_gemm<<<dim3(3, 16, 2), 256, MMA_SMEM>>>(s3);

    // 8) final scalars + layernorm
    final_kernel<<<NM, 128>>>(real, imag, W2r, b2r, W2i, b2i, g1, be1, out);
}

// round 16
// speedup vs baseline: 1.2353x; 1.0145x over previous
#include <cuda_runtime.h>
#include <cuda_bf16.h>
#include <cstdint>
#include <math.h>

#define NB 16
#define NT 128
#define ND 384
#define NH 6
#define NDH 64
#define NM 2048                 // NB*NT

#define CH   786432             // NM*ND
#define WSZ  1572864            // NB*NH*NT*NT
#define WW   147456             // ND*ND
#define A3W  768                // [XRE|XIM] concat width
#define A3SZ 1572864            // 2048*768 = 2*CH

// ---------------- fp32 scratch layout ----------------
#define OFF_IH  0
#define OFF_QR  6144
#define OFF_QI  (OFF_QR + CH)
#define OFF_KR  (OFF_QI + CH)
#define OFF_KI  (OFF_KR + CH)
#define OFF_VR  (OFF_KI + CH)
#define OFF_VI  (OFF_VR + CH)
#define OFF_GRE (OFF_VI + CH)
#define OFF_GIM (OFF_GRE + CH)
#define TOTALF  (OFF_GIM + CH)

// ---------------- bf16 scratch layout ----------------
#define BF_RH   0
#define BF_RL   ((size_t)CH)
#define BF_IMH  ((size_t)2*CH)
#define BF_IML  ((size_t)3*CH)
#define BF_ARH  ((size_t)4*CH)
#define BF_ARL  ((size_t)5*CH)
#define BF_AIH  ((size_t)6*CH)
#define BF_AIL  ((size_t)7*CH)
#define BF_A3H  ((size_t)8*CH)               // 2048 x 768 hi
#define BF_A3L  (BF_A3H + (size_t)A3SZ)      // lo
#define BF_W    (BF_A3L + (size_t)A3SZ)      // 4 weights (Wq,Wk,Wv,Wo) x (hi WW, lo WW)
#define BF_CATR (BF_W + 8*(size_t)WW)        // [W1r|-W1i] 384x768 hi,lo
#define BF_CATI (BF_CATR + 4*(size_t)WW)     // [W1i| W1r] 384x768 hi,lo
#define BF_Q    (BF_CATI + 4*(size_t)WW)     // 4 arrays (QR,QI,KR,KI) x (hi CH, lo CH)
#define TOTB    (BF_Q + 8*(size_t)CH)

__device__ float g_scratch[TOTALF];
__device__ __align__(16) __nv_bfloat16 g_bf[TOTB];

// ======================= helpers =======================
__device__ __forceinline__ uint32_t smem_u32(const void* p) {
    uint32_t a;
    asm("{ .reg .u64 t; cvta.to.shared.u64 t, %1; cvt.u32.u64 %0, t; }" : "=r"(a) : "l"(p));
    return a;
}

__device__ __forceinline__ float blocksum128(float v, float* sbuf) {
    #pragma unroll
    for (int o = 16; o; o >>= 1) v += __shfl_xor_sync(0xffffffffu, v, o);
    if ((threadIdx.x & 31) == 0) sbuf[threadIdx.x >> 5] = v;
    __syncthreads();
    float r = sbuf[0] + sbuf[1] + sbuf[2] + sbuf[3];
    __syncthreads();
    return r;
}
__device__ __forceinline__ float gelu_exact(float x) {
    return 0.5f * x * (1.0f + erff(x * 0.7071067811865475f));
}
__device__ __forceinline__ void split_store(__nv_bfloat16* ph, __nv_bfloat16* pl, float v) {
    __nv_bfloat16 h = __float2bfloat16(v);
    *ph = h;
    *pl = __float2bfloat16(v - __bfloat162float(h));
}

// 4-wide split: v[0..3] -> 8B hi pack + 8B lo pack
__device__ __forceinline__ void split4_store(__nv_bfloat16* ph, __nv_bfloat16* pl, float4 v) {
    __nv_bfloat16 h0 = __float2bfloat16(v.x), h1 = __float2bfloat16(v.y);
    __nv_bfloat16 h2 = __float2bfloat16(v.z), h3 = __float2bfloat16(v.w);
    __nv_bfloat162 hp0; hp0.x = h0; hp0.y = h1;
    __nv_bfloat162 hp1; hp1.x = h2; hp1.y = h3;
    __nv_bfloat162 lp0, lp1;
    lp0.x = __float2bfloat16(v.x - __bfloat162float(h0));
    lp0.y = __float2bfloat16(v.y - __bfloat162float(h1));
    lp1.x = __float2bfloat16(v.z - __bfloat162float(h2));
    lp1.y = __float2bfloat16(v.w - __bfloat162float(h3));
    uint2 hu, lu;
    hu.x = *reinterpret_cast<uint32_t*>(&hp0); hu.y = *reinterpret_cast<uint32_t*>(&hp1);
    lu.x = *reinterpret_cast<uint32_t*>(&lp0); lu.y = *reinterpret_cast<uint32_t*>(&lp1);
    *reinterpret_cast<uint2*>(ph) = hu;
    *reinterpret_cast<uint2*>(pl) = lu;
}

#define LDSM4(r0, r1, r2, r3, a) \
    asm volatile("ldmatrix.sync.aligned.m8n8.x4.shared.b16 {%0,%1,%2,%3}, [%4];" \
                 : "=r"(r0), "=r"(r1), "=r"(r2), "=r"(r3) : "r"(a))

#define LDSM4T(r0, r1, r2, r3, a) \
    asm volatile("ldmatrix.sync.aligned.m8n8.x4.trans.shared.b16 {%0,%1,%2,%3}, [%4];" \
                 : "=r"(r0), "=r"(r1), "=r"(r2), "=r"(r3) : "r"(a))

#define MMA16816(c, a, b) \
    asm volatile("mma.sync.aligned.m16n8k16.row.col.f32.bf16.bf16.f32 " \
                 "{%0,%1,%2,%3}, {%4,%5,%6,%7}, {%8,%9}, {%0,%1,%2,%3};" \
                 : "+f"((c)[0]), "+f"((c)[1]), "+f"((c)[2]), "+f"((c)[3]) \
                 : "r"((a)[0]), "r"((a)[1]), "r"((a)[2]), "r"((a)[3]), \
                   "r"((b)[0]), "r"((b)[1]))

#define CP_ASYNC16(dst, src) \
    asm volatile("cp.async.cg.shared.global [%0], [%1], 16;" :: "r"(dst), "l"(src))
#define CP_COMMIT() asm volatile("cp.async.commit_group;")
#define CP_WAIT1()  asm volatile("cp.async.wait_group 1;")
#define CP_WAIT0()  asm volatile("cp.async.wait_group 0;")

// ======================= mma.sync batched GEMM =======================
struct GemmOp {
    const __nv_bfloat16 *ah, *al, *bh, *bl;
    const float *bias, *bias2; float bscale, bscale2;
    float* out;
    __nv_bfloat16 *outh, *outl;
    int K, lda, ldo, gelu;
};
struct GemmBatch { GemmOp op[6]; };

#define SMS 40
#define MAT_ELE (128 * SMS)           // 5120
#define STG_ELE (4 * MAT_ELE)         // 20480
#define MMA_SMEM (2 * STG_ELE * 2)    // 81920 B

__global__ void __launch_bounds__(256, 2) mma_gemm(GemmBatch batch) {
    extern __shared__ __nv_bfloat16 sm[];
    uint32_t smb = smem_u32(sm);
    const GemmOp op = batch.op[blockIdx.z];
    const int tid = threadIdx.x, lane = tid & 31, warp = tid >> 5;
    const int m0 = blockIdx.y * 128, n0 = blockIdx.x * 128;
    const int m0w = (warp & 1) * 64, n0w = (warp >> 1) * 32;
    const int Kd = op.K, lda = op.lda;
    const int nchunks = Kd >> 5;

    const int aBase = (m0w + (lane & 15)) * SMS + (lane >> 4) * 8;
    const int bBase = (n0w + ((lane >> 4) & 1) * 8 + (lane & 7)) * SMS + ((lane >> 3) & 1) * 8;

    float acc[4][4][4];
    #pragma unroll
    for (int i = 0; i < 4; i++)
        #pragma unroll
        for (int j = 0; j < 4; j++)
            #pragma unroll
            for (int q = 0; q < 4; q++) acc[i][j][q] = 0.f;

    auto load_stage = [&](int c, int s) {
        int kc = c * 32;
        #pragma unroll
        for (int mat = 0; mat < 4; mat++) {
            const __nv_bfloat16* src = (mat == 0) ? op.ah : (mat == 1) ? op.al
                                     : (mat == 2) ? op.bh : op.bl;
            int rb = (mat < 2) ? m0 : n0;
            int stride = (mat < 2) ? lda : Kd;
            #pragma unroll
            for (int i = 0; i < 2; i++) {
                int l = tid + 256 * i;
                int row = l >> 2, c8 = l & 3;
                const __nv_bfloat16* g = src + (size_t)(rb + row) * stride + kc + c8 * 8;
                uint32_t d = smb + (uint32_t)(s * STG_ELE + mat * MAT_ELE + row * SMS + c8 * 8) * 2;
                CP_ASYNC16(d, g);
            }
        }
        CP_COMMIT();
    };

    load_stage(0, 0);

    for (int c = 0; c < nchunks; c++) {
        if (c + 1 < nchunks) { load_stage(c + 1, (c + 1) & 1); CP_WAIT1(); }
        else                 { CP_WAIT0(); }
        __syncthreads();

        uint32_t stb = smb + (uint32_t)((c & 1) * STG_ELE) * 2;
        #pragma unroll
        for (int ks = 0; ks < 2; ks++) {
            uint32_t bhf[4][2], blf[4][2];
            #pragma unroll
            for (int pr = 0; pr < 2; pr++) {
                uint32_t addr = stb + (uint32_t)(2 * MAT_ELE + bBase + pr * 16 * SMS + ks * 16) * 2;
                uint32_t r0, r1, r2, r3;
                LDSM4(r0, r1, r2, r3, addr);
                bhf[2*pr][0] = r0; bhf[2*pr][1] = r1;
                bhf[2*pr+1][0] = r2; bhf[2*pr+1][1] = r3;
                LDSM4(r0, r1, r2, r3, addr + MAT_ELE * 2);
                blf[2*pr][0] = r0; blf[2*pr][1] = r1;
                blf[2*pr+1][0] = r2; blf[2*pr+1][1] = r3;
            }
            #pragma unroll
            for (int mf = 0; mf < 4; mf++) {
                uint32_t ah4[4], al4[4];
                uint32_t addr = stb + (uint32_t)(aBase + mf * 16 * SMS + ks * 16) * 2;
                LDSM4(ah4[0], ah4[1], ah4[2], ah4[3], addr);
                LDSM4(al4[0], al4[1], al4[2], al4[3], addr + MAT_ELE * 2);
                #pragma unroll
                for (int nf = 0; nf < 4; nf++) {
                    MMA16816(acc[mf][nf], ah4, bhf[nf]);
                    MMA16816(acc[mf][nf], ah4, blf[nf]);
                    MMA16816(acc[mf][nf], al4, bhf[nf]);
                }
            }
        }
        __syncthreads();
    }

    #pragma unroll
    for (int mf = 0; mf < 4; mf++) {
        #pragma unroll
        for (int nf = 0; nf < 4; nf++) {
            int r0 = m0 + m0w + mf * 16 + (lane >> 2);
            int col = n0 + n0w + nf * 8 + (lane & 3) * 2;
            float v0 = acc[mf][nf][0], v1 = acc[mf][nf][1];
            float v2 = acc[mf][nf][2], v3 = acc[mf][nf][3];
            if (op.bias) {
                float bb0 = op.bscale * op.bias[col], bb1 = op.bscale * op.bias[col + 1];
                v0 += bb0; v1 += bb1; v2 += bb0; v3 += bb1;
            }
            if (op.bias2) {
                float bb0 = op.bscale2 * op.bias2[col], bb1 = op.bscale2 * op.bias2[col + 1];
                v0 += bb0; v1 += bb1; v2 += bb0; v3 += bb1;
            }
            if (op.gelu) {
                v0 = gelu_exact(v0); v1 = gelu_exact(v1);
                v2 = gelu_exact(v2); v3 = gelu_exact(v3);
            }
            if (op.out) {
                *reinterpret_cast<float2*>(op.out + (size_t)r0 * op.ldo + col)       = make_float2(v0, v1);
                *reinterpret_cast<float2*>(op.out + (size_t)(r0 + 8) * op.ldo + col) = make_float2(v2, v3);
            }
            if (op.outh) {
                __nv_bfloat16 h0 = __float2bfloat16(v0), h1 = __float2bfloat16(v1);
                __nv_bfloat16 h2 = __float2bfloat16(v2), h3 = __float2bfloat16(v3);
                __nv_bfloat162 hp0; hp0.x = h0; hp0.y = h1;
                __nv_bfloat162 hp1; hp1.x = h2; hp1.y = h3;
                __nv_bfloat162 lp0; lp0.x = __float2bfloat16(v0 - __bfloat162float(h0));
                                    lp0.y = __float2bfloat16(v1 - __bfloat162float(h1));
                __nv_bfloat162 lp1; lp1.x = __float2bfloat16(v2 - __bfloat162float(h2));
                                    lp1.y = __float2bfloat16(v3 - __bfloat162float(h3));
                size_t i0 = (size_t)r0 * op.ldo + col, i1 = (size_t)(r0 + 8) * op.ldo + col;
                *reinterpret_cast<__nv_bfloat162*>(op.outh + i0) = hp0;
                *reinterpret_cast<__nv_bfloat162*>(op.outh + i1) = hp1;
                *reinterpret_cast<__nv_bfloat162*>(op.outl + i0) = lp0;
                *reinterpret_cast<__nv_bfloat162*>(op.outl + i1) = lp1;
            }
        }
    }
}

// ======================= fused prep kernel, 4-wide (+ih) =======================
// blocks [0,1536): acts; [1536,2112): 4 weights; [2112,2400): W1 concat; [2400,2416): ih
__global__ void prep_all(const float* __restrict__ real, const float* __restrict__ imag,
                         const float* __restrict__ Wq, const float* __restrict__ Wk,
                         const float* __restrict__ Wv, const float* __restrict__ Wo,
                         const float* __restrict__ W1r, const float* __restrict__ W1i,
                         const float* __restrict__ iproj) {
    int bid = blockIdx.x, tid = threadIdx.x;
    if (bid < 1536) {
        int y = bid / 768;
        int i4 = ((bid - y * 768) * 256 + tid) * 4;
        const float* s = y ? imag : real;
        size_t o = y ? BF_IMH : BF_RH;
        float4 v = *reinterpret_cast<const float4*>(s + i4);
        split4_store(g_bf + o + i4, g_bf + o + CH + i4, v);
    } else if (bid < 2112) {
        int t = bid - 1536;
        int y = t / 144;
        int i4 = ((t - y * 144) * 256 + tid) * 4;
        const float* ws = (y == 0) ? Wq : (y == 1) ? Wk : (y == 2) ? Wv : Wo;
        size_t base = BF_W + (size_t)y * 2 * WW;
        float4 v = *reinterpret_cast<const float4*>(ws + i4);
        split4_store(g_bf + base + i4, g_bf + base + WW + i4, v);
    } else if (bid < 2400) {
        int i4 = ((bid - 2112) * 256 + tid) * 4;    // < 2*WW, 4-aligned within a row half
        int n = i4 / 768, k = i4 % 768;
        float4 vr, vi;
        if (k < 384) {
            float4 a = *reinterpret_cast<const float4*>(W1r + n*384 + k);
            float4 c = *reinterpret_cast<const float4*>(W1i + n*384 + k);
            vr = a; vi = c;
        } else {
            float4 c = *reinterpret_cast<const float4*>(W1i + n*384 + (k-384));
            float4 a = *reinterpret_cast<const float4*>(W1r + n*384 + (k-384));
            vr = make_float4(-c.x, -c.y, -c.z, -c.w);
            vi = a;
        }
        split4_store(g_bf + BF_CATR + i4, g_bf + BF_CATR + 2*(size_t)WW + i4, vr);
        split4_store(g_bf + BF_CATI + i4, g_bf + BF_CATI + 2*(size_t)WW + i4, vi);
    } else {
        int b = bid - 2400;
        __shared__ float sred[8];
        __shared__ float sn3;
        if (tid == 0) {
            float a = iproj[b*128+0], c = iproj[b*128+1], d = iproj[b*128+2];
            sn3 = sqrtf(a*a + c*c + d*d);
        }
        __syncthreads();
        float w = (tid < 128) ? (iproj[b*128 + tid] / sn3) : 0.f;
        float p = w * w;
        #pragma unroll
        for (int o = 16; o; o >>= 1) p += __shfl_xor_sync(0xffffffffu, p, o);
        if ((tid & 31) == 0) sred[tid >> 5] = p;
        __syncthreads();
        float sum = 0.f;
        #pragma unroll
        for (int ww = 0; ww < 8; ww++) sum += sred[ww];
        float nf = sqrtf(3.0f * sum);
        if (tid < 128) {
            float val = w / nf;
            float* ih = g_scratch + OFF_IH + b*ND;
            ih[tid] = val; ih[tid+128] = val; ih[tid+256] = val;
        }
    }
}

// ======================= K3: deflation -> bf16 hi/lo =======================
__global__ void ortho_kernel() {
    __shared__ float sbuf[4];
    int y = blockIdx.y;
    const float* arr = g_scratch + OFF_QR + (size_t)y * CH;
    __nv_bfloat16* oh = g_bf + BF_Q + (size_t)y * 2 * CH;
    __nv_bfloat16* ol = oh + CH;
    int row = blockIdx.x, t = threadIdx.x, b = row >> 7;
    const float* ih = g_scratch + OFF_IH + b*ND;
    float q0 = arr[row*ND + t], q1 = arr[row*ND + t + 128], q2 = arr[row*ND + t + 256];
    float i0 = ih[t], i1 = ih[t+128], i2 = ih[t+256];
    float dot = blocksum128(q0*i0 + q1*i1 + q2*i2, sbuf);
    split_store(oh + (size_t)row*ND + t,       ol + (size_t)row*ND + t,       q0 - dot*i0);
    split_store(oh + (size_t)row*ND + t + 128, ol + (size_t)row*ND + t + 128, q1 - dot*i1);
    split_store(oh + (size_t)row*ND + t + 256, ol + (size_t)row*ND + t + 256, q2 - dot*i2);
}

// ======================= K4: scores via mma.sync, register softmax =======================
#define QH_T 0
#define QL_T 9216
#define KH_T 18432
#define KL_T 27648
#define SC2_SMEM (73728 + 4096)

__global__ void __launch_bounds__(256, 2) scores_mma(float* __restrict__ wout) {
    extern __shared__ char smraw[];
    __nv_bfloat16* smb16 = reinterpret_cast<__nv_bfloat16*>(smraw);
    float* pm = reinterpret_cast<float*>(smraw + 73728);
    float* ps = pm + 512;
    uint32_t smb = smem_u32(smraw);
    int h = blockIdx.x, b = blockIdx.y, p = blockIdx.z, tid = threadIdx.x;
    int lane = tid & 31, warp = tid >> 5;

    const __nv_bfloat16* Qbase = g_bf + BF_Q + (size_t)(((p >> 1) & 1) * 2) * CH;
    const __nv_bfloat16* Kbase = g_bf + BF_Q + (size_t)((2 + (p & 1)) * 2) * CH;

    #pragma unroll
    for (int i = 0; i < 16; i++) {
        int l = tid + 256 * i;
        int mat = l >> 10, v = l & 1023;
        int row = v >> 3, col = (v & 7) * 8;
        const __nv_bfloat16* src = (mat == 0) ? Qbase : (mat == 1) ? Qbase + CH
                                  : (mat == 2) ? Kbase : Kbase + CH;
        const __nv_bfloat16* g = src + (size_t)(b*NT + row) * ND + h*NDH + col;
        uint32_t d = smb + (uint32_t)(mat * 9216 + row * 72 + col) * 2;
        CP_ASYNC16(d, g);
    }
    CP_COMMIT();
    CP_WAIT0();
    __syncthreads();

    const int mrow = (warp & 1) * 64, ncol = (warp >> 1) * 32;
    const int cg = warp >> 1;
    const int aBase = (mrow + (lane & 15)) * 72 + (lane >> 4) * 8;
    const int bBase = (ncol + ((lane >> 4) & 1) * 8 + (lane & 7)) * 72 + ((lane >> 3) & 1) * 8;

    float acc[4][4][4];
    #pragma unroll
    for (int i = 0; i < 4; i++)
        #pragma unroll
        for (int j = 0; j < 4; j++)
            #pragma unroll
            for (int q = 0; q < 4; q++) acc[i][j][q] = 0.f;

    #pragma unroll
    for (int ks = 0; ks < 4; ks++) {
        uint32_t bhf[4][2], blf[4][2];
        #pragma unroll
        for (int pr = 0; pr < 2; pr++) {
            uint32_t addr = smb + (uint32_t)(KH_T + bBase + pr * 16 * 72 + ks * 16) * 2;
            uint32_t r0, r1, r2, r3;
            LDSM4(r0, r1, r2, r3, addr);
            bhf[2*pr][0] = r0; bhf[2*pr][1] = r1;
            bhf[2*pr+1][0] = r2; bhf[2*pr+1][1] = r3;
            LDSM4(r0, r1, r2, r3, addr + (KL_T - KH_T) * 2);
            blf[2*pr][0] = r0; blf[2*pr][1] = r1;
            blf[2*pr+1][0] = r2; blf[2*pr+1][1] = r3;
        }
        #pragma unroll
        for (int mf = 0; mf < 4; mf++) {
            uint32_t ah4[4], al4[4];
            uint32_t addr = smb + (uint32_t)(QH_T + aBase + mf * 16 * 72 + ks * 16) * 2;
            LDSM4(ah4[0], ah4[1], ah4[2], ah4[3], addr);
            LDSM4(al4[0], al4[1], al4[2], al4[3], addr + (QL_T - QH_T) * 2);
            #pragma unroll
            for (int nf = 0; nf < 4; nf++) {
                MMA16816(acc[mf][nf], ah4, bhf[nf]);
                MMA16816(acc[mf][nf], ah4, blf[nf]);
                MMA16816(acc[mf][nf], al4, bhf[nf]);
            }
        }
    }

    #pragma unroll
    for (int mf = 0; mf < 4; mf++) {
        float m1 = -1e30f, m2 = -1e30f;
        #pragma unroll
        for (int nf = 0; nf < 4; nf++) {
            acc[mf][nf][0] *= 0.125f; acc[mf][nf][1] *= 0.125f;
            acc[mf][nf][2] *= 0.125f; acc[mf][nf][3] *= 0.125f;
            m1 = fmaxf(m1, fmaxf(acc[mf][nf][0], acc[mf][nf][1]));
            m2 = fmaxf(m2, fmaxf(acc[mf][nf][2], acc[mf][nf][3]));
        }
        m1 = fmaxf(m1, __shfl_xor_sync(0xffffffffu, m1, 1));
        m1 = fmaxf(m1, __shfl_xor_sync(0xffffffffu, m1, 2));
        m2 = fmaxf(m2, __shfl_xor_sync(0xffffffffu, m2, 1));
        m2 = fmaxf(m2, __shfl_xor_sync(0xffffffffu, m2, 2));
        if ((lane & 3) == 0) {
            int r1 = mrow + mf * 16 + (lane >> 2);
            pm[r1 * 4 + cg]       = m1;
            pm[(r1 + 8) * 4 + cg] = m2;
        }
    }
    __syncthreads();

    #pragma unroll
    for (int mf = 0; mf < 4; mf++) {
        int r1 = mrow + mf * 16 + (lane >> 2);
        float4 p1 = *reinterpret_cast<const float4*>(&pm[r1 * 4]);
        float4 p2 = *reinterpret_cast<const float4*>(&pm[(r1 + 8) * 4]);
        float mx1 = fmaxf(fmaxf(p1.x, p1.y), fmaxf(p1.z, p1.w));
        float mx2 = fmaxf(fmaxf(p2.x, p2.y), fmaxf(p2.z, p2.w));
        float s1 = 0.f, s2 = 0.f;
        #pragma unroll
        for (int nf = 0; nf < 4; nf++) {
            float e0 = __expf(acc[mf][nf][0] - mx1);
            float e1 = __expf(acc[mf][nf][1] - mx1);
            float e2 = __expf(acc[mf][nf][2] - mx2);
            float e3 = __expf(acc[mf][nf][3] - mx2);
            acc[mf][nf][0] = e0; acc[mf][nf][1] = e1;
            acc[mf][nf][2] = e2; acc[mf][nf][3] = e3;
            s1 += e0 + e1; s2 += e2 + e3;
        }
        s1 += __shfl_xor_sync(0xffffffffu, s1, 1);
        s1 += __shfl_xor_sync(0xffffffffu, s1, 2);
        s2 += __shfl_xor_sync(0xffffffffu, s2, 1);
        s2 += __shfl_xor_sync(0xffffffffu, s2, 2);
        if ((lane & 3) == 0) {
            ps[r1 * 4 + cg]       = s1;
            ps[(r1 + 8) * 4 + cg] = s2;
        }
    }
    __syncthreads();

    const int s1t[4] = {0, 2, 3, 6};
    const int s2t[4] = {1, 4, 5, 7};
    float* o1 = wout + (size_t)s1t[p]*WSZ;
    float* o2 = wout + (size_t)s2t[p]*WSZ;
    #pragma unroll
    for (int mf = 0; mf < 4; mf++) {
        int r1 = mrow + mf * 16 + (lane >> 2);
        float4 q1 = *reinterpret_cast<const float4*>(&ps[r1 * 4]);
        float4 q2 = *reinterpret_cast<const float4*>(&ps[(r1 + 8) * 4]);
        float inv1 = 1.0f / (q1.x + q1.y + q1.z + q1.w);
        float inv2 = 1.0f / (q2.x + q2.y + q2.z + q2.w);
        size_t base1 = (((size_t)b*NH + h)*NT + r1)*NT;
        size_t base2 = base1 + 8 * NT;
        #pragma unroll
        for (int nf = 0; nf < 4; nf++) {
            int col = ncol + nf * 8 + (lane & 3) * 2;
            float2 w1 = make_float2(acc[mf][nf][0] * inv1, acc[mf][nf][1] * inv1);
            float2 w2 = make_float2(acc[mf][nf][2] * inv2, acc[mf][nf][3] * inv2);
            *reinterpret_cast<float2*>(o1 + base1 + col) = w1;
            *reinterpret_cast<float2*>(o2 + base1 + col) = w1;
            *reinterpret_cast<float2*>(o1 + base2 + col) = w2;
            *reinterpret_cast<float2*>(o2 + base2 + col) = w2;
        }
    }
}

// ======================= K5: attention x V via mma.sync =======================
#define AVW 136
#define AVV 72
#define AVM_SMEM (90112 * 2)   // 180224 B

__global__ void __launch_bounds__(256) av_mma(const float* __restrict__ wout) {
    extern __shared__ __nv_bfloat16 smav[];
    uint32_t smb = smem_u32(smav);
    int qt = blockIdx.x, h = blockIdx.y, b = blockIdx.z, tid = threadIdx.x;
    int lane = tid & 31, warp = tid >> 5;

    for (int i = tid; i < 8192; i += 256) {
        int q = i >> 7, k = i & 127;
        size_t idx = (((size_t)b*NH + h)*NT + qt*64 + q)*NT + k;
        float w0 = wout[idx];
        float w6 = wout[6*(size_t)WSZ + idx];
        float w2 = wout[2*(size_t)WSZ + idx];
        float w3 = wout[3*(size_t)WSZ + idx];
        float wa  = w0 - w6;
        float wbn = -(w2 + w3);
        int off = q * AVW + k;
        split_store(smav + off,         smav + 8704  + off, wa);
        split_store(smav + 17408 + off, smav + 26112 + off, wbn);
    }
    const float* Vr = g_scratch + OFF_VR;
    const float* Vi = g_scratch + OFF_VI;
    for (int i = tid; i < 8192; i += 256) {
        int k = i >> 6, d = i & 63;
        int gi = (b*NT + k)*ND + h*NDH + d;
        int off = k * AVV + d;
        split_store(smav + 34816 + off, smav + 44032 + off, Vr[gi]);
        float vi = Vi[gi];
        __nv_bfloat16 vih = __float2bfloat16(vi);
        __nv_bfloat16 vil = __float2bfloat16(vi - __bfloat162float(vih));
        smav[53248 + off] = vih;           smav[62464 + off] = vil;
        smav[71680 + off] = __hneg(vih);   smav[80896 + off] = __hneg(vil);
    }
    __syncthreads();

    const int m0w = (warp & 1) * 32, d0 = (warp >> 1) * 16;
    const int aBase = (m0w + (lane & 15)) * AVW + (lane >> 4) * 8;
    const int bOff = (lane & 15) * AVV + d0 + (lane >> 4) * 8;

    float accR[2][2][4], accI[2][2][4];
    #pragma unroll
    for (int i = 0; i < 2; i++)
        #pragma unroll
        for (int j = 0; j < 2; j++)
            #pragma unroll
            for (int q = 0; q < 4; q++) { accR[i][j][q] = 0.f; accI[i][j][q] = 0.f; }

    #pragma unroll
    for (int ks = 0; ks < 8; ks++) {
        uint32_t vrh[2][2], vrl[2][2], vih[2][2], vil[2][2], vnh[2][2], vnl[2][2];
        {
            uint32_t base = smb + (uint32_t)(34816 + ks*16*AVV + bOff) * 2;
            uint32_t r0,r1,r2,r3;
            LDSM4T(r0,r1,r2,r3, base);
            vrh[0][0]=r0; vrh[0][1]=r1; vrh[1][0]=r2; vrh[1][1]=r3;
            LDSM4T(r0,r1,r2,r3, base + 9216*2);
            vrl[0][0]=r0; vrl[0][1]=r1; vrl[1][0]=r2; vrl[1][1]=r3;
            LDSM4T(r0,r1,r2,r3, base + 18432*2);
            vih[0][0]=r0; vih[0][1]=r1; vih[1][0]=r2; vih[1][1]=r3;
            LDSM4T(r0,r1,r2,r3, base + 27648*2);
            vil[0][0]=r0; vil[0][1]=r1; vil[1][0]=r2; vil[1][1]=r3;
            LDSM4T(r0,r1,r2,r3, base + 36864*2);
            vnh[0][0]=r0; vnh[0][1]=r1; vnh[1][0]=r2; vnh[1][1]=r3;
            LDSM4T(r0,r1,r2,r3, base + 46080*2);
            vnl[0][0]=r0; vnl[0][1]=r1; vnl[1][0]=r2; vnl[1][1]=r3;
        }
        #pragma unroll
        for (int mf = 0; mf < 2; mf++) {
            uint32_t wah[4], wal[4], wbh[4], wbl[4];
            uint32_t addr = smb + (uint32_t)(aBase + mf*16*AVW + ks*16) * 2;
            LDSM4(wah[0], wah[1], wah[2], wah[3], addr);
            LDSM4(wal[0], wal[1], wal[2], wal[3], addr + 8704*2);
            LDSM4(wbh[0], wbh[1], wbh[2], wbh[3], addr + 17408*2);
            LDSM4(wbl[0], wbl[1], wbl[2], wbl[3], addr + 26112*2);
            #pragma unroll
            for (int nf = 0; nf < 2; nf++) {
                MMA16816(accR[mf][nf], wah, vrh[nf]);
                MMA16816(accR[mf][nf], wah, vrl[nf]);
                MMA16816(accR[mf][nf], wal, vrh[nf]);
                MMA16816(accR[mf][nf], wbh, vih[nf]);
                MMA16816(accR[mf][nf], wbh, vil[nf]);
                MMA16816(accR[mf][nf], wbl, vih[nf]);
                MMA16816(accI[mf][nf], wbh, vrh[nf]);
                MMA16816(accI[mf][nf], wbh, vrl[nf]);
                MMA16816(accI[mf][nf], wbl, vrh[nf]);
                MMA16816(accI[mf][nf], wah, vnh[nf]);
                MMA16816(accI[mf][nf], wah, vnl[nf]);
                MMA16816(accI[mf][nf], wal, vnh[nf]);
            }
        }
    }

    #pragma unroll
    for (int mf = 0; mf < 2; mf++) {
        #pragma unroll
        for (int nf = 0; nf < 2; nf++) {
            int r = m0w + mf * 16 + (lane >> 2);
            int d = d0 + nf * 8 + (lane & 3) * 2;
            int q = qt * 64 + r;
            size_t go0 = (size_t)(b*NT + q) * ND + h*NDH + d;
            size_t go1 = go0 + (size_t)8 * ND;
            split_store(g_bf + BF_ARH + go0,     g_bf + BF_ARL + go0,     accR[mf][nf][0]);
            split_store(g_bf + BF_ARH + go0 + 1, g_bf + BF_ARL + go0 + 1, accR[mf][nf][1]);
            split_store(g_bf + BF_ARH + go1,     g_bf + BF_ARL + go1,     accR[mf][nf][2]);
            split_store(g_bf + BF_ARH + go1 + 1, g_bf + BF_ARL + go1 + 1, accR[mf][nf][3]);
            split_store(g_bf + BF_AIH + go0,     g_bf + BF_AIL + go0,     -accI[mf][nf][0]);
            split_store(g_bf + BF_AIH + go0 + 1, g_bf + BF_AIL + go0 + 1, -accI[mf][nf][1]);
            split_store(g_bf + BF_AIH + go1,     g_bf + BF_AIL + go1,     -accI[mf][nf][2]);
            split_store(g_bf + BF_AIH + go1 + 1, g_bf + BF_AIL + go1 + 1, -accI[mf][nf][3]);
        }
    }
}

// ======================= K9: final scalars + layernorm =======================
__global__ void final_kernel(const float* __restrict__ real, const float* __restrict__ imag,
                             const float* __restrict__ W2r, const float* __restrict__ b2r,
                             const float* __restrict__ W2i, const float* __restrict__ b2i,
                             const float* __restrict__ g1,  const float* __restrict__ be1,
                             float* __restrict__ out) {
    int row = blockIdx.x, t = threadIdx.x;
    __shared__ float sbuf[4];
    const float* gre = g_scratch + OFF_GRE + (size_t)row*ND;
    const float* gim = g_scratch + OFF_GIM + (size_t)row*ND;
    const float* re  = real + (size_t)row*ND;
    const float* im  = imag + (size_t)row*ND;

    float grev[3], gimv[3], rev[3], imv[3], w2rv[3], w2iv[3];
    #pragma unroll
    for (int j = 0; j < 3; j++) {
        int d = t + 128*j;
        grev[j] = gre[d]; gimv[j] = gim[d];
        rev[j]  = re[d];  imv[j]  = im[d];
        w2rv[j] = W2r[d]; w2iv[j] = W2i[d];
    }
    float p0=0,p1=0,p2=0,p3=0,p4=0,p5=0;
    #pragma unroll
    for (int j = 0; j < 3; j++) {
        p0 += grev[j]*w2rv[j];
        p1 += gimv[j]*w2iv[j];
        p2 += gimv[j]*w2rv[j];
        p3 += grev[j]*w2iv[j];
        p4 += rev[j]*rev[j] + imv[j]*imv[j];
        p5 -= (rev[j] + imv[j]) * imv[j];
    }
    float d0 = blocksum128(p0, sbuf);
    float d1 = blocksum128(p1, sbuf);
    float d2 = blocksum128(p2, sbuf);
    float d3 = blocksum128(p3, sbuf);
    float d4 = blocksum128(p4, sbuf);
    float d5 = blocksum128(p5, sbuf);

    float sre  = d0 + b2r[0] - (d1 + b2i[0]);
    float sim  = d2 + b2r[0] + (d3 + b2i[0]);
    float s2   = sre*sre + sim*sim;
    float simn = -(s2*sim) - sim*sim;
    float denom = d4*d4 + d5*d5;
    float Wc = (s2*d4 + simn*d5) / denom;

    float xr[3], xi[3];
    #pragma unroll
    for (int j = 0; j < 3; j++) {
        xr[j] = Wc * (rev[j] - imv[j]);
        xi[j] = 2.0f * Wc * imv[j];
    }
    float mr = blocksum128(xr[0]+xr[1]+xr[2], sbuf) * (1.0f/ND);
    float vrp = 0.f;
    #pragma unroll
    for (int j = 0; j < 3; j++) { float dd = xr[j]-mr; vrp += dd*dd; }
    float vr = blocksum128(vrp, sbuf) * (1.0f/ND);
    float rsr = rsqrtf(vr + 1e-5f);
    float mi = blocksum128(xi[0]+xi[1]+xi[2], sbuf) * (1.0f/ND);
    float vip = 0.f;
    #pragma unroll
    for (int j = 0; j < 3; j++) { float dd = xi[j]-mi; vip += dd*dd; }
    float vi = blocksum128(vip, sbuf) * (1.0f/ND);
    float rsi = rsqrtf(vi + 1e-5f);

    #pragma unroll
    for (int j = 0; j < 3; j++) {
        int d = t + 128*j;
        out[(size_t)row*ND + d]      = (xr[j]-mr)*rsr*g1[d] + be1[d];
        out[CH + (size_t)row*ND + d] = (xi[j]-mi)*rsi*g1[d] + be1[d];
    }
}

// ======================= host launcher =======================
extern "C" void kernel_launch(void* const* d_in, const int* in_sizes, int n_in,
                              void* d_out, int out_size) {
    const float* real  = (const float*)d_in[0];
    const float* imag  = (const float*)d_in[1];
    const float* iproj = (const float*)d_in[2];
    const float* Wq = (const float*)d_in[3];  const float* bq = (const float*)d_in[4];
    const float* Wk = (const float*)d_in[5];  const float* bk = (const float*)d_in[6];
    const float* Wv = (const float*)d_in[7];  const float* bv = (const float*)d_in[8];
    const float* Wo = (const float*)d_in[9];  const float* bo = (const float*)d_in[10];
    const float* W1r = (const float*)d_in[11]; const float* b1r = (const float*)d_in[12];
    const float* W1i = (const float*)d_in[13]; const float* b1i = (const float*)d_in[14];
    const float* W2r = (const float*)d_in[15]; const float* b2r = (const float*)d_in[16];
    const float* W2i = (const float*)d_in[17]; const float* b2i = (const float*)d_in[18];
    const float* g1  = (const float*)d_in[19]; const float* be1 = (const float*)d_in[20];
    float* out = (float*)d_out;

    float* S = nullptr;
    __nv_bfloat16* Bp = nullptr;
    cudaGetSymbolAddress((void**)&S, g_scratch);
    cudaGetSymbolAddress((void**)&Bp, g_bf);

    cudaFuncSetAttribute(scores_mma, cudaFuncAttributeMaxDynamicSharedMemorySize, SC2_SMEM);
    cudaFuncSetAttribute(av_mma,     cudaFuncAttributeMaxDynamicSharedMemorySize, AVM_SMEM);
    cudaFuncSetAttribute(mma_gemm,   cudaFuncAttributeMaxDynamicSharedMemorySize, MMA_SMEM);

    __nv_bfloat16* WH[4]; __nv_bfloat16* WL[4];
    for (int y = 0; y < 4; y++) {
        WH[y] = Bp + BF_W + (size_t)y * 2 * WW;
        WL[y] = WH[y] + WW;
    }
    __nv_bfloat16* CRH = Bp + BF_CATR;            __nv_bfloat16* CRL = CRH + 2*(size_t)WW;
    __nv_bfloat16* CIH = Bp + BF_CATI;            __nv_bfloat16* CIL = CIH + 2*(size_t)WW;

    // 1) fused prep (4-wide vectorized)
    prep_all<<<2416, 256>>>(real, imag, Wq, Wk, Wv, Wo, W1r, W1i, iproj);

    // 2) stage-1: six projection GEMMs
    GemmBatch s1;
    const __nv_bfloat16* AH2[2] = { Bp + BF_RH, Bp + BF_IMH };
    const __nv_bfloat16* AL2[2] = { Bp + BF_RL, Bp + BF_IML };
    const float* biases[3] = { bq, bk, bv };
    size_t outs[6] = { OFF_QR, OFF_QI, OFF_KR, OFF_KI, OFF_VR, OFF_VI };
    for (int o = 0; o < 6; o++) {
        int w = o >> 1, a = o & 1;
        s1.op[o] = { AH2[a], AL2[a], WH[w], WL[w], biases[w], nullptr, 1.0f, 0.f,
                     S + outs[o], nullptr, nullptr, ND, ND, ND, 0 };
    }
    mma_gemm<<<dim3(3, 16, 6), 256, MMA_SMEM>>>(s1);

    // 3) deflate Q/K -> bf16 hi/lo
    ortho_kernel<<<dim3(NM, 4), 128>>>();

    // 4) scores via mma + register softmax
    scores_mma<<<dim3(NH, NB, 4), 256, SC2_SMEM>>>(out + 2*(size_t)CH);

    // 5) attention x V via mma
    av_mma<<<dim3(2, NH, NB), 256, AVM_SMEM>>>(out + 2*(size_t)CH);

    // 6) stage-2: Wo GEMMs -> A3 [XRE | XIM]
    GemmBatch s2;
    s2.op[0] = { Bp + BF_ARH, Bp + BF_ARL, WH[3], WL[3], bo, nullptr, -2.0f, 0.f,
                 nullptr, Bp + BF_A3H, Bp + BF_A3L, ND, ND, A3W, 0 };
    s2.op[1] = { Bp + BF_AIH, Bp + BF_AIL, WH[3], WL[3], bo, nullptr,  2.0f, 0.f,
                 nullptr, Bp + BF_A3H + 384, Bp + BF_A3L + 384, ND, ND, A3W, 0 };
    mma_gemm<<<dim3(3, 16, 2), 256, MMA_SMEM>>>(s2);

    // 7) stage-3: fused W1 complex layer + bias + GELU
    GemmBatch s3;
    s3.op[0] = { Bp + BF_A3H, Bp + BF_A3L, CRH, CRL, b1r, b1i, 1.0f, -1.0f,
                 S + OFF_GRE, nullptr, nullptr, A3W, A3W, ND, 1 };
    s3.op[1] = { Bp + BF_A3H, Bp + BF_A3L, CIH, CIL, b1r, b1i, 1.0f,  1.0f,
                 S + OFF_GIM, nullptr, nullptr, A3W, A3W, ND, 1 };
    mma_gemm<<<dim3(3, 16, 2), 256, MMA_SMEM>>>(s3);

    // 8) final scalars + layernorm
    final_kernel<<<NM, 128>>>(real, imag, W2r, b2r, W2i, b2i, g1, be1, out);
}

// round 17
// speedup vs baseline: 1.2667x; 1.0254x over previous
#include <cuda_runtime.h>
#include <cuda_bf16.h>
#include <cstdint>
#include <math.h>

#define NB 16
#define NT 128
#define ND 384
#define NH 6
#define NDH 64
#define NM 2048                 // NB*NT

#define CH   786432             // NM*ND
#define WSZ  1572864            // NB*NH*NT*NT
#define WW   147456             // ND*ND
#define A3W  768                // [XRE|XIM] concat width
#define A3SZ 1572864            // 2048*768 = 2*CH

// ---------------- fp32 scratch layout ----------------
#define OFF_IH  0
#define OFF_QR  6144
#define OFF_QI  (OFF_QR + CH)
#define OFF_KR  (OFF_QI + CH)
#define OFF_KI  (OFF_KR + CH)
#define OFF_VR  (OFF_KI + CH)
#define OFF_VI  (OFF_VR + CH)
#define OFF_GRE (OFF_VI + CH)
#define OFF_GIM (OFF_GRE + CH)
#define TOTALF  (OFF_GIM + CH)

// ---------------- bf16 scratch layout ----------------
#define BF_RH   0
#define BF_RL   ((size_t)CH)
#define BF_IMH  ((size_t)2*CH)
#define BF_IML  ((size_t)3*CH)
#define BF_ARH  ((size_t)4*CH)
#define BF_ARL  ((size_t)5*CH)
#define BF_AIH  ((size_t)6*CH)
#define BF_AIL  ((size_t)7*CH)
#define BF_A3H  ((size_t)8*CH)               // 2048 x 768 hi
#define BF_A3L  (BF_A3H + (size_t)A3SZ)      // lo
#define BF_W    (BF_A3L + (size_t)A3SZ)      // 4 weights (Wq,Wk,Wv,Wo) x (hi WW, lo WW)
#define BF_CATR (BF_W + 8*(size_t)WW)        // [W1r|-W1i] 384x768 hi,lo
#define BF_CATI (BF_CATR + 4*(size_t)WW)     // [W1i| W1r] 384x768 hi,lo
#define BF_Q    (BF_CATI + 4*(size_t)WW)     // 4 arrays (QR,QI,KR,KI) x (hi CH, lo CH)
#define TOTB    (BF_Q + 8*(size_t)CH)

__device__ float g_scratch[TOTALF];
__device__ __align__(16) __nv_bfloat16 g_bf[TOTB];

// ======================= helpers =======================
__device__ __forceinline__ uint32_t smem_u32(const void* p) {
    uint32_t a;
    asm("{ .reg .u64 t; cvta.to.shared.u64 t, %1; cvt.u32.u64 %0, t; }" : "=r"(a) : "l"(p));
    return a;
}

__device__ __forceinline__ float warpsum(float v) {
    #pragma unroll
    for (int o = 16; o; o >>= 1) v += __shfl_xor_sync(0xffffffffu, v, o);
    return v;
}
__device__ __forceinline__ float gelu_exact(float x) {
    return 0.5f * x * (1.0f + erff(x * 0.7071067811865475f));
}
__device__ __forceinline__ void split_store(__nv_bfloat16* ph, __nv_bfloat16* pl, float v) {
    __nv_bfloat16 h = __float2bfloat16(v);
    *ph = h;
    *pl = __float2bfloat16(v - __bfloat162float(h));
}

// 4-wide split: v[0..3] -> 8B hi pack + 8B lo pack
__device__ __forceinline__ void split4_store(__nv_bfloat16* ph, __nv_bfloat16* pl, float4 v) {
    __nv_bfloat16 h0 = __float2bfloat16(v.x), h1 = __float2bfloat16(v.y);
    __nv_bfloat16 h2 = __float2bfloat16(v.z), h3 = __float2bfloat16(v.w);
    __nv_bfloat162 hp0; hp0.x = h0; hp0.y = h1;
    __nv_bfloat162 hp1; hp1.x = h2; hp1.y = h3;
    __nv_bfloat162 lp0, lp1;
    lp0.x = __float2bfloat16(v.x - __bfloat162float(h0));
    lp0.y = __float2bfloat16(v.y - __bfloat162float(h1));
    lp1.x = __float2bfloat16(v.z - __bfloat162float(h2));
    lp1.y = __float2bfloat16(v.w - __bfloat162float(h3));
    uint2 hu, lu;
    hu.x = *reinterpret_cast<uint32_t*>(&hp0); hu.y = *reinterpret_cast<uint32_t*>(&hp1);
    lu.x = *reinterpret_cast<uint32_t*>(&lp0); lu.y = *reinterpret_cast<uint32_t*>(&lp1);
    *reinterpret_cast<uint2*>(ph) = hu;
    *reinterpret_cast<uint2*>(pl) = lu;
}

#define LDSM4(r0, r1, r2, r3, a) \
    asm volatile("ldmatrix.sync.aligned.m8n8.x4.shared.b16 {%0,%1,%2,%3}, [%4];" \
                 : "=r"(r0), "=r"(r1), "=r"(r2), "=r"(r3) : "r"(a))

#define LDSM4T(r0, r1, r2, r3, a) \
    asm volatile("ldmatrix.sync.aligned.m8n8.x4.trans.shared.b16 {%0,%1,%2,%3}, [%4];" \
                 : "=r"(r0), "=r"(r1), "=r"(r2), "=r"(r3) : "r"(a))

#define MMA16816(c, a, b) \
    asm volatile("mma.sync.aligned.m16n8k16.row.col.f32.bf16.bf16.f32 " \
                 "{%0,%1,%2,%3}, {%4,%5,%6,%7}, {%8,%9}, {%0,%1,%2,%3};" \
                 : "+f"((c)[0]), "+f"((c)[1]), "+f"((c)[2]), "+f"((c)[3]) \
                 : "r"((a)[0]), "r"((a)[1]), "r"((a)[2]), "r"((a)[3]), \
                   "r"((b)[0]), "r"((b)[1]))

#define CP_ASYNC16(dst, src) \
    asm volatile("cp.async.cg.shared.global [%0], [%1], 16;" :: "r"(dst), "l"(src))
#define CP_COMMIT() asm volatile("cp.async.commit_group;")
#define CP_WAIT1()  asm volatile("cp.async.wait_group 1;")
#define CP_WAIT0()  asm volatile("cp.async.wait_group 0;")

// ======================= mma.sync batched GEMM =======================
struct GemmOp {
    const __nv_bfloat16 *ah, *al, *bh, *bl;
    const float *bias, *bias2; float bscale, bscale2;
    float* out;
    __nv_bfloat16 *outh, *outl;
    int K, lda, ldo, gelu;
};
struct GemmBatch { GemmOp op[6]; };

#define SMS 40
#define MAT_ELE (128 * SMS)           // 5120
#define STG_ELE (4 * MAT_ELE)         // 20480
#define MMA_SMEM (2 * STG_ELE * 2)    // 81920 B

__global__ void __launch_bounds__(256, 2) mma_gemm(GemmBatch batch) {
    extern __shared__ __nv_bfloat16 sm[];
    uint32_t smb = smem_u32(sm);
    const GemmOp op = batch.op[blockIdx.z];
    const int tid = threadIdx.x, lane = tid & 31, warp = tid >> 5;
    const int m0 = blockIdx.y * 128, n0 = blockIdx.x * 128;
    const int m0w = (warp & 1) * 64, n0w = (warp >> 1) * 32;
    const int Kd = op.K, lda = op.lda;
    const int nchunks = Kd >> 5;

    const int aBase = (m0w + (lane & 15)) * SMS + (lane >> 4) * 8;
    const int bBase = (n0w + ((lane >> 4) & 1) * 8 + (lane & 7)) * SMS + ((lane >> 3) & 1) * 8;

    float acc[4][4][4];
    #pragma unroll
    for (int i = 0; i < 4; i++)
        #pragma unroll
        for (int j = 0; j < 4; j++)
            #pragma unroll
            for (int q = 0; q < 4; q++) acc[i][j][q] = 0.f;

    auto load_stage = [&](int c, int s) {
        int kc = c * 32;
        #pragma unroll
        for (int mat = 0; mat < 4; mat++) {
            const __nv_bfloat16* src = (mat == 0) ? op.ah : (mat == 1) ? op.al
                                     : (mat == 2) ? op.bh : op.bl;
            int rb = (mat < 2) ? m0 : n0;
            int stride = (mat < 2) ? lda : Kd;
            #pragma unroll
            for (int i = 0; i < 2; i++) {
                int l = tid + 256 * i;
                int row = l >> 2, c8 = l & 3;
                const __nv_bfloat16* g = src + (size_t)(rb + row) * stride + kc + c8 * 8;
                uint32_t d = smb + (uint32_t)(s * STG_ELE + mat * MAT_ELE + row * SMS + c8 * 8) * 2;
                CP_ASYNC16(d, g);
            }
        }
        CP_COMMIT();
    };

    load_stage(0, 0);

    for (int c = 0; c < nchunks; c++) {
        if (c + 1 < nchunks) { load_stage(c + 1, (c + 1) & 1); CP_WAIT1(); }
        else                 { CP_WAIT0(); }
        __syncthreads();

        uint32_t stb = smb + (uint32_t)((c & 1) * STG_ELE) * 2;
        #pragma unroll
        for (int ks = 0; ks < 2; ks++) {
            uint32_t bhf[4][2], blf[4][2];
            #pragma unroll
            for (int pr = 0; pr < 2; pr++) {
                uint32_t addr = stb + (uint32_t)(2 * MAT_ELE + bBase + pr * 16 * SMS + ks * 16) * 2;
                uint32_t r0, r1, r2, r3;
                LDSM4(r0, r1, r2, r3, addr);
                bhf[2*pr][0] = r0; bhf[2*pr][1] = r1;
                bhf[2*pr+1][0] = r2; bhf[2*pr+1][1] = r3;
                LDSM4(r0, r1, r2, r3, addr + MAT_ELE * 2);
                blf[2*pr][0] = r0; blf[2*pr][1] = r1;
                blf[2*pr+1][0] = r2; blf[2*pr+1][1] = r3;
            }
            #pragma unroll
            for (int mf = 0; mf < 4; mf++) {
                uint32_t ah4[4], al4[4];
                uint32_t addr = stb + (uint32_t)(aBase + mf * 16 * SMS + ks * 16) * 2;
                LDSM4(ah4[0], ah4[1], ah4[2], ah4[3], addr);
                LDSM4(al4[0], al4[1], al4[2], al4[3], addr + MAT_ELE * 2);
                #pragma unroll
                for (int nf = 0; nf < 4; nf++) {
                    MMA16816(acc[mf][nf], ah4, bhf[nf]);
                    MMA16816(acc[mf][nf], ah4, blf[nf]);
                    MMA16816(acc[mf][nf], al4, bhf[nf]);
                }
            }
        }
        __syncthreads();
    }

    #pragma unroll
    for (int mf = 0; mf < 4; mf++) {
        #pragma unroll
        for (int nf = 0; nf < 4; nf++) {
            int r0 = m0 + m0w + mf * 16 + (lane >> 2);
            int col = n0 + n0w + nf * 8 + (lane & 3) * 2;
            float v0 = acc[mf][nf][0], v1 = acc[mf][nf][1];
            float v2 = acc[mf][nf][2], v3 = acc[mf][nf][3];
            if (op.bias) {
                float bb0 = op.bscale * op.bias[col], bb1 = op.bscale * op.bias[col + 1];
                v0 += bb0; v1 += bb1; v2 += bb0; v3 += bb1;
            }
            if (op.bias2) {
                float bb0 = op.bscale2 * op.bias2[col], bb1 = op.bscale2 * op.bias2[col + 1];
                v0 += bb0; v1 += bb1; v2 += bb0; v3 += bb1;
            }
            if (op.gelu) {
                v0 = gelu_exact(v0); v1 = gelu_exact(v1);
                v2 = gelu_exact(v2); v3 = gelu_exact(v3);
            }
            if (op.out) {
                *reinterpret_cast<float2*>(op.out + (size_t)r0 * op.ldo + col)       = make_float2(v0, v1);
                *reinterpret_cast<float2*>(op.out + (size_t)(r0 + 8) * op.ldo + col) = make_float2(v2, v3);
            }
            if (op.outh) {
                __nv_bfloat16 h0 = __float2bfloat16(v0), h1 = __float2bfloat16(v1);
                __nv_bfloat16 h2 = __float2bfloat16(v2), h3 = __float2bfloat16(v3);
                __nv_bfloat162 hp0; hp0.x = h0; hp0.y = h1;
                __nv_bfloat162 hp1; hp1.x = h2; hp1.y = h3;
                __nv_bfloat162 lp0; lp0.x = __float2bfloat16(v0 - __bfloat162float(h0));
                                    lp0.y = __float2bfloat16(v1 - __bfloat162float(h1));
                __nv_bfloat162 lp1; lp1.x = __float2bfloat16(v2 - __bfloat162float(h2));
                                    lp1.y = __float2bfloat16(v3 - __bfloat162float(h3));
                size_t i0 = (size_t)r0 * op.ldo + col, i1 = (size_t)(r0 + 8) * op.ldo + col;
                *reinterpret_cast<__nv_bfloat162*>(op.outh + i0) = hp0;
                *reinterpret_cast<__nv_bfloat162*>(op.outh + i1) = hp1;
                *reinterpret_cast<__nv_bfloat162*>(op.outl + i0) = lp0;
                *reinterpret_cast<__nv_bfloat162*>(op.outl + i1) = lp1;
            }
        }
    }
}

// ======================= fused prep kernel, 4-wide (+ih) =======================
__global__ void prep_all(const float* __restrict__ real, const float* __restrict__ imag,
                         const float* __restrict__ Wq, const float* __restrict__ Wk,
                         const float* __restrict__ Wv, const float* __restrict__ Wo,
                         const float* __restrict__ W1r, const float* __restrict__ W1i,
                         const float* __restrict__ iproj) {
    int bid = blockIdx.x, tid = threadIdx.x;
    if (bid < 1536) {
        int y = bid / 768;
        int i4 = ((bid - y * 768) * 256 + tid) * 4;
        const float* s = y ? imag : real;
        size_t o = y ? BF_IMH : BF_RH;
        float4 v = *reinterpret_cast<const float4*>(s + i4);
        split4_store(g_bf + o + i4, g_bf + o + CH + i4, v);
    } else if (bid < 2112) {
        int t = bid - 1536;
        int y = t / 144;
        int i4 = ((t - y * 144) * 256 + tid) * 4;
        const float* ws = (y == 0) ? Wq : (y == 1) ? Wk : (y == 2) ? Wv : Wo;
        size_t base = BF_W + (size_t)y * 2 * WW;
        float4 v = *reinterpret_cast<const float4*>(ws + i4);
        split4_store(g_bf + base + i4, g_bf + base + WW + i4, v);
    } else if (bid < 2400) {
        int i4 = ((bid - 2112) * 256 + tid) * 4;
        int n = i4 / 768, k = i4 % 768;
        float4 vr, vi;
        if (k < 384) {
            float4 a = *reinterpret_cast<const float4*>(W1r + n*384 + k);
            float4 c = *reinterpret_cast<const float4*>(W1i + n*384 + k);
            vr = a; vi = c;
        } else {
            float4 c = *reinterpret_cast<const float4*>(W1i + n*384 + (k-384));
            float4 a = *reinterpret_cast<const float4*>(W1r + n*384 + (k-384));
            vr = make_float4(-c.x, -c.y, -c.z, -c.w);
            vi = a;
        }
        split4_store(g_bf + BF_CATR + i4, g_bf + BF_CATR + 2*(size_t)WW + i4, vr);
        split4_store(g_bf + BF_CATI + i4, g_bf + BF_CATI + 2*(size_t)WW + i4, vi);
    } else {
        int b = bid - 2400;
        __shared__ float sred[8];
        __shared__ float sn3;
        if (tid == 0) {
            float a = iproj[b*128+0], c = iproj[b*128+1], d = iproj[b*128+2];
            sn3 = sqrtf(a*a + c*c + d*d);
        }
        __syncthreads();
        float w = (tid < 128) ? (iproj[b*128 + tid] / sn3) : 0.f;
        float p = warpsum(w * w);
        if ((tid & 31) == 0) sred[tid >> 5] = p;
        __syncthreads();
        float sum = 0.f;
        #pragma unroll
        for (int ww = 0; ww < 8; ww++) sum += sred[ww];
        float nf = sqrtf(3.0f * sum);
        if (tid < 128) {
            float val = w / nf;
            float* ih = g_scratch + OFF_IH + b*ND;
            ih[tid] = val; ih[tid+128] = val; ih[tid+256] = val;
        }
    }
}

// ======================= K3: deflation, warp-per-row =======================
// block = 256 threads = 8 warps; warp handles one row. grid (NM/8, 4)
__global__ void __launch_bounds__(256) ortho_kernel() {
    int y = blockIdx.y;                      // 0=QR 1=QI 2=KR 3=KI
    int warp = threadIdx.x >> 5, lane = threadIdx.x & 31;
    int row = blockIdx.x * 8 + warp, b = row >> 7;
    const float* arr = g_scratch + OFF_QR + (size_t)y * CH + (size_t)row * ND;
    __nv_bfloat16* oh = g_bf + BF_Q + (size_t)y * 2 * CH + (size_t)row * ND;
    __nv_bfloat16* ol = oh + CH;
    const float* ih = g_scratch + OFF_IH + b * ND;

    float4 q[3], iv[3];
    #pragma unroll
    for (int s = 0; s < 3; s++) {
        int col = lane * 4 + s * 128;
        q[s]  = *reinterpret_cast<const float4*>(arr + col);
        iv[s] = *reinterpret_cast<const float4*>(ih + col);
    }
    float p = 0.f;
    #pragma unroll
    for (int s = 0; s < 3; s++)
        p += q[s].x*iv[s].x + q[s].y*iv[s].y + q[s].z*iv[s].z + q[s].w*iv[s].w;
    float dot = warpsum(p);

    #pragma unroll
    for (int s = 0; s < 3; s++) {
        int col = lane * 4 + s * 128;
        float4 r = make_float4(q[s].x - dot*iv[s].x, q[s].y - dot*iv[s].y,
                               q[s].z - dot*iv[s].z, q[s].w - dot*iv[s].w);
        split4_store(oh + col, ol + col, r);
    }
}

// ======================= K4: scores via mma.sync, register softmax =======================
#define QH_T 0
#define QL_T 9216
#define KH_T 18432
#define KL_T 27648
#define SC2_SMEM (73728 + 4096)

__global__ void __launch_bounds__(256, 2) scores_mma(float* __restrict__ wout) {
    extern __shared__ char smraw[];
    __nv_bfloat16* smb16 = reinterpret_cast<__nv_bfloat16*>(smraw);
    float* pm = reinterpret_cast<float*>(smraw + 73728);
    float* ps = pm + 512;
    uint32_t smb = smem_u32(smraw);
    int h = blockIdx.x, b = blockIdx.y, p = blockIdx.z, tid = threadIdx.x;
    int lane = tid & 31, warp = tid >> 5;

    const __nv_bfloat16* Qbase = g_bf + BF_Q + (size_t)(((p >> 1) & 1) * 2) * CH;
    const __nv_bfloat16* Kbase = g_bf + BF_Q + (size_t)((2 + (p & 1)) * 2) * CH;

    #pragma unroll
    for (int i = 0; i < 16; i++) {
        int l = tid + 256 * i;
        int mat = l >> 10, v = l & 1023;
        int row = v >> 3, col = (v & 7) * 8;
        const __nv_bfloat16* src = (mat == 0) ? Qbase : (mat == 1) ? Qbase + CH
                                  : (mat == 2) ? Kbase : Kbase + CH;
        const __nv_bfloat16* g = src + (size_t)(b*NT + row) * ND + h*NDH + col;
        uint32_t d = smb + (uint32_t)(mat * 9216 + row * 72 + col) * 2;
        CP_ASYNC16(d, g);
    }
    CP_COMMIT();
    CP_WAIT0();
    __syncthreads();

    const int mrow = (warp & 1) * 64, ncol = (warp >> 1) * 32;
    const int cg = warp >> 1;
    const int aBase = (mrow + (lane & 15)) * 72 + (lane >> 4) * 8;
    const int bBase = (ncol + ((lane >> 4) & 1) * 8 + (lane & 7)) * 72 + ((lane >> 3) & 1) * 8;

    float acc[4][4][4];
    #pragma unroll
    for (int i = 0; i < 4; i++)
        #pragma unroll
        for (int j = 0; j < 4; j++)
            #pragma unroll
            for (int q = 0; q < 4; q++) acc[i][j][q] = 0.f;

    #pragma unroll
    for (int ks = 0; ks < 4; ks++) {
        uint32_t bhf[4][2], blf[4][2];
        #pragma unroll
        for (int pr = 0; pr < 2; pr++) {
            uint32_t addr = smb + (uint32_t)(KH_T + bBase + pr * 16 * 72 + ks * 16) * 2;
            uint32_t r0, r1, r2, r3;
            LDSM4(r0, r1, r2, r3, addr);
            bhf[2*pr][0] = r0; bhf[2*pr][1] = r1;
            bhf[2*pr+1][0] = r2; bhf[2*pr+1][1] = r3;
            LDSM4(r0, r1, r2, r3, addr + (KL_T - KH_T) * 2);
            blf[2*pr][0] = r0; blf[2*pr][1] = r1;
            blf[2*pr+1][0] = r2; blf[2*pr+1][1] = r3;
        }
        #pragma unroll
        for (int mf = 0; mf < 4; mf++) {
            uint32_t ah4[4], al4[4];
            uint32_t addr = smb + (uint32_t)(QH_T + aBase + mf * 16 * 72 + ks * 16) * 2;
            LDSM4(ah4[0], ah4[1], ah4[2], ah4[3], addr);
            LDSM4(al4[0], al4[1], al4[2], al4[3], addr + (QL_T - QH_T) * 2);
            #pragma unroll
            for (int nf = 0; nf < 4; nf++) {
                MMA16816(acc[mf][nf], ah4, bhf[nf]);
                MMA16816(acc[mf][nf], ah4, blf[nf]);
                MMA16816(acc[mf][nf], al4, bhf[nf]);
            }
        }
    }

    #pragma unroll
    for (int mf = 0; mf < 4; mf++) {
        float m1 = -1e30f, m2 = -1e30f;
        #pragma unroll
        for (int nf = 0; nf < 4; nf++) {
            acc[mf][nf][0] *= 0.125f; acc[mf][nf][1] *= 0.125f;
            acc[mf][nf][2] *= 0.125f; acc[mf][nf][3] *= 0.125f;
            m1 = fmaxf(m1, fmaxf(acc[mf][nf][0], acc[mf][nf][1]));
            m2 = fmaxf(m2, fmaxf(acc[mf][nf][2], acc[mf][nf][3]));
        }
        m1 = fmaxf(m1, __shfl_xor_sync(0xffffffffu, m1, 1));
        m1 = fmaxf(m1, __shfl_xor_sync(0xffffffffu, m1, 2));
        m2 = fmaxf(m2, __shfl_xor_sync(0xffffffffu, m2, 1));
        m2 = fmaxf(m2, __shfl_xor_sync(0xffffffffu, m2, 2));
        if ((lane & 3) == 0) {
            int r1 = mrow + mf * 16 + (lane >> 2);
            pm[r1 * 4 + cg]       = m1;
            pm[(r1 + 8) * 4 + cg] = m2;
        }
    }
    __syncthreads();

    #pragma unroll
    for (int mf = 0; mf < 4; mf++) {
        int r1 = mrow + mf * 16 + (lane >> 2);
        float4 p1 = *reinterpret_cast<const float4*>(&pm[r1 * 4]);
        float4 p2 = *reinterpret_cast<const float4*>(&pm[(r1 + 8) * 4]);
        float mx1 = fmaxf(fmaxf(p1.x, p1.y), fmaxf(p1.z, p1.w));
        float mx2 = fmaxf(fmaxf(p2.x, p2.y), fmaxf(p2.z, p2.w));
        float s1 = 0.f, s2 = 0.f;
        #pragma unroll
        for (int nf = 0; nf < 4; nf++) {
            float e0 = __expf(acc[mf][nf][0] - mx1);
            float e1 = __expf(acc[mf][nf][1] - mx1);
            float e2 = __expf(acc[mf][nf][2] - mx2);
            float e3 = __expf(acc[mf][nf][3] - mx2);
            acc[mf][nf][0] = e0; acc[mf][nf][1] = e1;
            acc[mf][nf][2] = e2; acc[mf][nf][3] = e3;
            s1 += e0 + e1; s2 += e2 + e3;
        }
        s1 += __shfl_xor_sync(0xffffffffu, s1, 1);
        s1 += __shfl_xor_sync(0xffffffffu, s1, 2);
        s2 += __shfl_xor_sync(0xffffffffu, s2, 1);
        s2 += __shfl_xor_sync(0xffffffffu, s2, 2);
        if ((lane & 3) == 0) {
            ps[r1 * 4 + cg]       = s1;
            ps[(r1 + 8) * 4 + cg] = s2;
        }
    }
    __syncthreads();

    const int s1t[4] = {0, 2, 3, 6};
    const int s2t[4] = {1, 4, 5, 7};
    float* o1 = wout + (size_t)s1t[p]*WSZ;
    float* o2 = wout + (size_t)s2t[p]*WSZ;
    #pragma unroll
    for (int mf = 0; mf < 4; mf++) {
        int r1 = mrow + mf * 16 + (lane >> 2);
        float4 q1 = *reinterpret_cast<const float4*>(&ps[r1 * 4]);
        float4 q2 = *reinterpret_cast<const float4*>(&ps[(r1 + 8) * 4]);
        float inv1 = 1.0f / (q1.x + q1.y + q1.z + q1.w);
        float inv2 = 1.0f / (q2.x + q2.y + q2.z + q2.w);
        size_t base1 = (((size_t)b*NH + h)*NT + r1)*NT;
        size_t base2 = base1 + 8 * NT;
        #pragma unroll
        for (int nf = 0; nf < 4; nf++) {
            int col = ncol + nf * 8 + (lane & 3) * 2;
            float2 w1 = make_float2(acc[mf][nf][0] * inv1, acc[mf][nf][1] * inv1);
            float2 w2 = make_float2(acc[mf][nf][2] * inv2, acc[mf][nf][3] * inv2);
            *reinterpret_cast<float2*>(o1 + base1 + col) = w1;
            *reinterpret_cast<float2*>(o2 + base1 + col) = w1;
            *reinterpret_cast<float2*>(o1 + base2 + col) = w2;
            *reinterpret_cast<float2*>(o2 + base2 + col) = w2;
        }
    }
}

// ======================= K5: attention x V via mma.sync =======================
#define AVW 136
#define AVV 72
#define AVM_SMEM (90112 * 2)   // 180224 B

__global__ void __launch_bounds__(256) av_mma(const float* __restrict__ wout) {
    extern __shared__ __nv_bfloat16 smav[];
    uint32_t smb = smem_u32(smav);
    int qt = blockIdx.x, h = blockIdx.y, b = blockIdx.z, tid = threadIdx.x;
    int lane = tid & 31, warp = tid >> 5;

    for (int i = tid; i < 8192; i += 256) {
        int q = i >> 7, k = i & 127;
        size_t idx = (((size_t)b*NH + h)*NT + qt*64 + q)*NT + k;
        float w0 = wout[idx];
        float w6 = wout[6*(size_t)WSZ + idx];
        float w2 = wout[2*(size_t)WSZ + idx];
        float w3 = wout[3*(size_t)WSZ + idx];
        float wa  = w0 - w6;
        float wbn = -(w2 + w3);
        int off = q * AVW + k;
        split_store(smav + off,         smav + 8704  + off, wa);
        split_store(smav + 17408 + off, smav + 26112 + off, wbn);
    }
    const float* Vr = g_scratch + OFF_VR;
    const float* Vi = g_scratch + OFF_VI;
    for (int i = tid; i < 8192; i += 256) {
        int k = i >> 6, d = i & 63;
        int gi = (b*NT + k)*ND + h*NDH + d;
        int off = k * AVV + d;
        split_store(smav + 34816 + off, smav + 44032 + off, Vr[gi]);
        float vi = Vi[gi];
        __nv_bfloat16 vih = __float2bfloat16(vi);
        __nv_bfloat16 vil = __float2bfloat16(vi - __bfloat162float(vih));
        smav[53248 + off] = vih;           smav[62464 + off] = vil;
        smav[71680 + off] = __hneg(vih);   smav[80896 + off] = __hneg(vil);
    }
    __syncthreads();

    const int m0w = (warp & 1) * 32, d0 = (warp >> 1) * 16;
    const int aBase = (m0w + (lane & 15)) * AVW + (lane >> 4) * 8;
    const int bOff = (lane & 15) * AVV + d0 + (lane >> 4) * 8;

    float accR[2][2][4], accI[2][2][4];
    #pragma unroll
    for (int i = 0; i < 2; i++)
        #pragma unroll
        for (int j = 0; j < 2; j++)
            #pragma unroll
            for (int q = 0; q < 4; q++) { accR[i][j][q] = 0.f; accI[i][j][q] = 0.f; }

    #pragma unroll
    for (int ks = 0; ks < 8; ks++) {
        uint32_t vrh[2][2], vrl[2][2], vih[2][2], vil[2][2], vnh[2][2], vnl[2][2];
        {
            uint32_t base = smb + (uint32_t)(34816 + ks*16*AVV + bOff) * 2;
            uint32_t r0,r1,r2,r3;
            LDSM4T(r0,r1,r2,r3, base);
            vrh[0][0]=r0; vrh[0][1]=r1; vrh[1][0]=r2; vrh[1][1]=r3;
            LDSM4T(r0,r1,r2,r3, base + 9216*2);
            vrl[0][0]=r0; vrl[0][1]=r1; vrl[1][0]=r2; vrl[1][1]=r3;
            LDSM4T(r0,r1,r2,r3, base + 18432*2);
            vih[0][0]=r0; vih[0][1]=r1; vih[1][0]=r2; vih[1][1]=r3;
            LDSM4T(r0,r1,r2,r3, base + 27648*2);
            vil[0][0]=r0; vil[0][1]=r1; vil[1][0]=r2; vil[1][1]=r3;
            LDSM4T(r0,r1,r2,r3, base + 36864*2);
            vnh[0][0]=r0; vnh[0][1]=r1; vnh[1][0]=r2; vnh[1][1]=r3;
            LDSM4T(r0,r1,r2,r3, base + 46080*2);
            vnl[0][0]=r0; vnl[0][1]=r1; vnl[1][0]=r2; vnl[1][1]=r3;
        }
        #pragma unroll
        for (int mf = 0; mf < 2; mf++) {
            uint32_t wah[4], wal[4], wbh[4], wbl[4];
            uint32_t addr = smb + (uint32_t)(aBase + mf*16*AVW + ks*16) * 2;
            LDSM4(wah[0], wah[1], wah[2], wah[3], addr);
            LDSM4(wal[0], wal[1], wal[2], wal[3], addr + 8704*2);
            LDSM4(wbh[0], wbh[1], wbh[2], wbh[3], addr + 17408*2);
            LDSM4(wbl[0], wbl[1], wbl[2], wbl[3], addr + 26112*2);
            #pragma unroll
            for (int nf = 0; nf < 2; nf++) {
                MMA16816(accR[mf][nf], wah, vrh[nf]);
                MMA16816(accR[mf][nf], wah, vrl[nf]);
                MMA16816(accR[mf][nf], wal, vrh[nf]);
                MMA16816(accR[mf][nf], wbh, vih[nf]);
                MMA16816(accR[mf][nf], wbh, vil[nf]);
                MMA16816(accR[mf][nf], wbl, vih[nf]);
                MMA16816(accI[mf][nf], wbh, vrh[nf]);
                MMA16816(accI[mf][nf], wbh, vrl[nf]);
                MMA16816(accI[mf][nf], wbl, vrh[nf]);
                MMA16816(accI[mf][nf], wah, vnh[nf]);
                MMA16816(accI[mf][nf], wah, vnl[nf]);
                MMA16816(accI[mf][nf], wal, vnh[nf]);
            }
        }
    }

    #pragma unroll
    for (int mf = 0; mf < 2; mf++) {
        #pragma unroll
        for (int nf = 0; nf < 2; nf++) {
            int r = m0w + mf * 16 + (lane >> 2);
            int d = d0 + nf * 8 + (lane & 3) * 2;
            int q = qt * 64 + r;
            size_t go0 = (size_t)(b*NT + q) * ND + h*NDH + d;
            size_t go1 = go0 + (size_t)8 * ND;
            split_store(g_bf + BF_ARH + go0,     g_bf + BF_ARL + go0,     accR[mf][nf][0]);
            split_store(g_bf + BF_ARH + go0 + 1, g_bf + BF_ARL + go0 + 1, accR[mf][nf][1]);
            split_store(g_bf + BF_ARH + go1,     g_bf + BF_ARL + go1,     accR[mf][nf][2]);
            split_store(g_bf + BF_ARH + go1 + 1, g_bf + BF_ARL + go1 + 1, accR[mf][nf][3]);
            split_store(g_bf + BF_AIH + go0,     g_bf + BF_AIL + go0,     -accI[mf][nf][0]);
            split_store(g_bf + BF_AIH + go0 + 1, g_bf + BF_AIL + go0 + 1, -accI[mf][nf][1]);
            split_store(g_bf + BF_AIH + go1,     g_bf + BF_AIL + go1,     -accI[mf][nf][2]);
            split_store(g_bf + BF_AIH + go1 + 1, g_bf + BF_AIL + go1 + 1, -accI[mf][nf][3]);
        }
    }
}

// ======================= K9: final scalars + layernorm, warp-per-row =======================
// block = 128 threads = 4 warps; warp handles one row; grid = NM/4
__global__ void __launch_bounds__(128) final_kernel(
        const float* __restrict__ real, const float* __restrict__ imag,
        const float* __restrict__ W2r, const float* __restrict__ b2r,
        const float* __restrict__ W2i, const float* __restrict__ b2i,
        const float* __restrict__ g1,  const float* __restrict__ be1,
        float* __restrict__ out) {
    int warp = threadIdx.x >> 5, lane = threadIdx.x & 31;
    int row = blockIdx.x * 4 + warp;
    const float* gre = g_scratch + OFF_GRE + (size_t)row*ND;
    const float* gim = g_scratch + OFF_GIM + (size_t)row*ND;
    const float* re  = real + (size_t)row*ND;
    const float* im  = imag + (size_t)row*ND;

    float4 grev[3], gimv[3], rev[3], imv[3], w2rv[3], w2iv[3];
    #pragma unroll
    for (int s = 0; s < 3; s++) {
        int col = lane * 4 + s * 128;
        grev[s] = *reinterpret_cast<const float4*>(gre + col);
        gimv[s] = *reinterpret_cast<const float4*>(gim + col);
        rev[s]  = *reinterpret_cast<const float4*>(re + col);
        imv[s]  = *reinterpret_cast<const float4*>(im + col);
        w2rv[s] = *reinterpret_cast<const float4*>(W2r + col);
        w2iv[s] = *reinterpret_cast<const float4*>(W2i + col);
    }
    float p0=0,p1=0,p2=0,p3=0,p4=0,p5=0;
    #pragma unroll
    for (int s = 0; s < 3; s++) {
        p0 += grev[s].x*w2rv[s].x + grev[s].y*w2rv[s].y + grev[s].z*w2rv[s].z + grev[s].w*w2rv[s].w;
        p1 += gimv[s].x*w2iv[s].x + gimv[s].y*w2iv[s].y + gimv[s].z*w2iv[s].z + gimv[s].w*w2iv[s].w;
        p2 += gimv[s].x*w2rv[s].x + gimv[s].y*w2rv[s].y + gimv[s].z*w2rv[s].z + gimv[s].w*w2rv[s].w;
        p3 += grev[s].x*w2iv[s].x + grev[s].y*w2iv[s].y + grev[s].z*w2iv[s].z + grev[s].w*w2iv[s].w;
        p4 += rev[s].x*rev[s].x + imv[s].x*imv[s].x + rev[s].y*rev[s].y + imv[s].y*imv[s].y
            + rev[s].z*rev[s].z + imv[s].z*imv[s].z + rev[s].w*rev[s].w + imv[s].w*imv[s].w;
        p5 -= (rev[s].x + imv[s].x)*imv[s].x + (rev[s].y + imv[s].y)*imv[s].y
            + (rev[s].z + imv[s].z)*imv[s].z + (rev[s].w + imv[s].w)*imv[s].w;
    }
    float d0 = warpsum(p0);
    float d1 = warpsum(p1);
    float d2 = warpsum(p2);
    float d3 = warpsum(p3);
    float d4 = warpsum(p4);   // F_re
    float d5 = warpsum(p5);   // F_im

    float sre  = d0 + b2r[0] - (d1 + b2i[0]);
    float sim  = d2 + b2r[0] + (d3 + b2i[0]);
    float s2   = sre*sre + sim*sim;
    float simn = -(s2*sim) - sim*sim;
    float denom = d4*d4 + d5*d5;
    float Wc = (s2*d4 + simn*d5) / denom;

    float xr[12], xi[12];
    #pragma unroll
    for (int s = 0; s < 3; s++) {
        const float* rp = &rev[s].x;
        const float* ip = &imv[s].x;
        #pragma unroll
        for (int j = 0; j < 4; j++) {
            xr[s*4 + j] = Wc * (rp[j] - ip[j]);
            xi[s*4 + j] = 2.0f * Wc * ip[j];
        }
    }
    float sr = 0.f, si = 0.f;
    #pragma unroll
    for (int j = 0; j < 12; j++) { sr += xr[j]; si += xi[j]; }
    float mr = warpsum(sr) * (1.0f/ND);
    float mi = warpsum(si) * (1.0f/ND);
    float vrp = 0.f, vip = 0.f;
    #pragma unroll
    for (int j = 0; j < 12; j++) {
        float dr = xr[j]-mr; vrp += dr*dr;
        float di = xi[j]-mi; vip += di*di;
    }
    float vr = warpsum(vrp) * (1.0f/ND);
    float vi = warpsum(vip) * (1.0f/ND);
    float rsr = rsqrtf(vr + 1e-5f);
    float rsi = rsqrtf(vi + 1e-5f);

    #pragma unroll
    for (int s = 0; s < 3; s++) {
        int col = lane * 4 + s * 128;
        float4 gv = *reinterpret_cast<const float4*>(g1 + col);
        float4 bv = *reinterpret_cast<const float4*>(be1 + col);
        float4 o1, o2;
        o1.x = (xr[s*4+0]-mr)*rsr*gv.x + bv.x;
        o1.y = (xr[s*4+1]-mr)*rsr*gv.y + bv.y;
        o1.z = (xr[s*4+2]-mr)*rsr*gv.z + bv.z;
        o1.w = (xr[s*4+3]-mr)*rsr*gv.w + bv.w;
        o2.x = (xi[s*4+0]-mi)*rsi*gv.x + bv.x;
        o2.y = (xi[s*4+1]-mi)*rsi*gv.y + bv.y;
        o2.z = (xi[s*4+2]-mi)*rsi*gv.z + bv.z;
        o2.w = (xi[s*4+3]-mi)*rsi*gv.w + bv.w;
        *reinterpret_cast<float4*>(out + (size_t)row*ND + col)      = o1;
        *reinterpret_cast<float4*>(out + CH + (size_t)row*ND + col) = o2;
    }
}

// ======================= host launcher =======================
extern "C" void kernel_launch(void* const* d_in, const int* in_sizes, int n_in,
                              void* d_out, int out_size) {
    const float* real  = (const float*)d_in[0];
    const float* imag  = (const float*)d_in[1];
    const float* iproj = (const float*)d_in[2];
    const float* Wq = (const float*)d_in[3];  const float* bq = (const float*)d_in[4];
    const float* Wk = (const float*)d_in[5];  const float* bk = (const float*)d_in[6];
    const float* Wv = (const float*)d_in[7];  const float* bv = (const float*)d_in[8];
    const float* Wo = (const float*)d_in[9];  const float* bo = (const float*)d_in[10];
    const float* W1r = (const float*)d_in[11]; const float* b1r = (const float*)d_in[12];
    const float* W1i = (const float*)d_in[13]; const float* b1i = (const float*)d_in[14];
    const float* W2r = (const float*)d_in[15]; const float* b2r = (const float*)d_in[16];
    const float* W2i = (const float*)d_in[17]; const float* b2i = (const float*)d_in[18];
    const float* g1  = (const float*)d_in[19]; const float* be1 = (const float*)d_in[20];
    float* out = (float*)d_out;

    float* S = nullptr;
    __nv_bfloat16* Bp = nullptr;
    cudaGetSymbolAddress((void**)&S, g_scratch);
    cudaGetSymbolAddress((void**)&Bp, g_bf);

    cudaFuncSetAttribute(scores_mma, cudaFuncAttributeMaxDynamicSharedMemorySize, SC2_SMEM);
    cudaFuncSetAttribute(av_mma,     cudaFuncAttributeMaxDynamicSharedMemorySize, AVM_SMEM);
    cudaFuncSetAttribute(mma_gemm,   cudaFuncAttributeMaxDynamicSharedMemorySize, MMA_SMEM);

    __nv_bfloat16* WH[4]; __nv_bfloat16* WL[4];
    for (int y = 0; y < 4; y++) {
        WH[y] = Bp + BF_W + (size_t)y * 2 * WW;
        WL[y] = WH[y] + WW;
    }
    __nv_bfloat16* CRH = Bp + BF_CATR;            __nv_bfloat16* CRL = CRH + 2*(size_t)WW;
    __nv_bfloat16* CIH = Bp + BF_CATI;            __nv_bfloat16* CIL = CIH + 2*(size_t)WW;

    // 1) fused prep (4-wide vectorized)
    prep_all<<<2416, 256>>>(real, imag, Wq, Wk, Wv, Wo, W1r, W1i, iproj);

    // 2) stage-1: six projection GEMMs
    GemmBatch s1;
    const __nv_bfloat16* AH2[2] = { Bp + BF_RH, Bp + BF_IMH };
    const __nv_bfloat16* AL2[2] = { Bp + BF_RL, Bp + BF_IML };
    const float* biases[3] = { bq, bk, bv };
    size_t outs[6] = { OFF_QR, OFF_QI, OFF_KR, OFF_KI, OFF_VR, OFF_VI };
    for (int o = 0; o < 6; o++) {
        int w = o >> 1, a = o & 1;
        s1.op[o] = { AH2[a], AL2[a], WH[w], WL[w], biases[w], nullptr, 1.0f, 0.f,
                     S + outs[o], nullptr, nullptr, ND, ND, ND, 0 };
    }
    mma_gemm<<<dim3(3, 16, 6), 256, MMA_SMEM>>>(s1);

    // 3) deflate Q/K -> bf16 hi/lo (warp-per-row)
    ortho_kernel<<<dim3(NM/8, 4), 256>>>();

    // 4) scores via mma + register softmax
    scores_mma<<<dim3(NH, NB, 4), 256, SC2_SMEM>>>(out + 2*(size_t)CH);

    // 5) attention x V via mma
    av_mma<<<dim3(2, NH, NB), 256, AVM_SMEM>>>(out + 2*(size_t)CH);

    // 6) stage-2: Wo GEMMs -> A3 [XRE | XIM]
    GemmBatch s2;
    s2.op[0] = { Bp + BF_ARH, Bp + BF_ARL, WH[3], WL[3], bo, nullptr, -2.0f, 0.f,
                 nullptr, Bp + BF_A3H, Bp + BF_A3L, ND, ND, A3W, 0 };
    s2.op[1] = { Bp + BF_AIH, Bp + BF_AIL, WH[3], WL[3], bo, nullptr,  2.0f, 0.f,
                 nullptr, Bp + BF_A3H + 384, Bp + BF_A3L + 384, ND, ND, A3W, 0 };
    mma_gemm<<<dim3(3, 16, 2), 256, MMA_SMEM>>>(s2);

    // 7) stage-3: fused W1 complex layer + bias + GELU
    GemmBatch s3;
    s3.op[0] = { Bp + BF_A3H, Bp + BF_A3L, CRH, CRL, b1r, b1i, 1.0f, -1.0f,
                 S + OFF_GRE, nullptr, nullptr, A3W, A3W, ND, 1 };
    s3.op[1] = { Bp + BF_A3H, Bp + BF_A3L, CIH, CIL, b1r, b1i, 1.0f,  1.0f,
                 S + OFF_GIM, nullptr, nullptr, A3W, A3W, ND, 1 };
    mma_gemm<<<dim3(3, 16, 2), 256, MMA_SMEM>>>(s3);

    // 8) final scalars + layernorm (warp-per-row)
    final_kernel<<<NM/4, 128>>>(real, imag, W2r, b2r, W2i, b2i, g1, be1, out);
}